// round 2
// baseline (speedup 1.0000x reference)
#include <cuda_runtime.h>
#include <cuda_bf16.h>
#include <math.h>

// Problem constants
#define BATCH 2
#define TT 2048
#define MM 512
#define CC 512
#define HH 8
#define DD 64
#define SCALE 0.125f   // 1/sqrt(64)

// ---------------- scratch (device globals; no allocation allowed) -------------
__device__ float g_qkv_x[(long)BATCH*TT*3*CC];        // [4096,1536]
__device__ float g_qkv_y[(long)BATCH*MM*3*CC];        // [1024,1536]
__device__ float g_catt_x2y[(long)BATCH*HH*TT*MM];    // [B,H,T,M] raw scores
__device__ float g_p_x2y[(long)BATCH*HH*TT*MM];       // softmax of above
__device__ float g_catt_y2x[(long)BATCH*HH*MM*TT];    // [B,H,M,T]
__device__ float g_big[(long)BATCH*HH*TT*TT];         // [B,H,T,T] prod / satt (reused)
__device__ float g_cval[(long)BATCH*TT*CC];
__device__ float g_sval[(long)BATCH*TT*CC];
__device__ float g_t1[(long)BATCH*TT*CC];
__device__ float g_t2[(long)BATCH*TT*CC];
__device__ float g_t3[(long)BATCH*TT*CC];

// ---------------- generic tiled fp32 GEMM ------------------------------------
// C[i,j] = alpha * sum_k A[i,k] * op(B)[k,j]  (+ bias[j])  (+= if ACC)
// Batched over blockIdx.z with z = b*Hn + h; per-matrix offset = b*s?b + h*s?h.
#define BM 64
#define BN 64
#define BK 16
#define LDS 68   // padded smem row stride (floats); 68*4B = 272B = 17*16B (16B aligned)

template<bool TB, bool ACC, bool BIAS>
__global__ void __launch_bounds__(256) gemm_k(
    const float* __restrict__ A, const float* __restrict__ Bm,
    float* __restrict__ C, const float* __restrict__ bias,
    int Mg, int Ng, int Kg, int lda, int ldb, int ldc,
    long sAb, long sAh, long sBb, long sBh, long sCb, long sCh,
    int Hn, float alpha)
{
    int z = blockIdx.z;
    int bb = z / Hn, hh = z - bb * Hn;
    A  += (long)bb * sAb + (long)hh * sAh;
    Bm += (long)bb * sBb + (long)hh * sBh;
    C  += (long)bb * sCb + (long)hh * sCh;

    __shared__ __align__(16) float As[BK][LDS];
    __shared__ __align__(16) float Bs[BK][LDS];

    int tid = threadIdx.x;
    int tx = tid & 15, ty = tid >> 4;
    int m0 = blockIdx.y * BM, n0 = blockIdx.x * BN;

    float acc[4][4] = {};

    for (int k0 = 0; k0 < Kg; k0 += BK) {
        // load A tile: 64 rows x 16 k  (16 threads per row, coalesced 64B/row)
        #pragma unroll
        for (int l = 0; l < 4; ++l) {
            int idx = tid + l * 256;
            int r = idx >> 4, kk = idx & 15;
            As[kk][r] = A[(long)(m0 + r) * lda + (k0 + kk)];
        }
        if (TB) {
            #pragma unroll
            for (int l = 0; l < 4; ++l) {
                int idx = tid + l * 256;
                int c = idx >> 4, kk = idx & 15;
                Bs[kk][c] = Bm[(long)(n0 + c) * ldb + (k0 + kk)];
            }
        } else {
            #pragma unroll
            for (int l = 0; l < 4; ++l) {
                int idx = tid + l * 256;
                int kk = idx >> 6, c = idx & 63;
                Bs[kk][c] = Bm[(long)(k0 + kk) * ldb + (n0 + c)];
            }
        }
        __syncthreads();

        #pragma unroll
        for (int kk = 0; kk < BK; ++kk) {
            float4 a4 = *(const float4*)&As[kk][ty * 4];
            float4 b4 = *(const float4*)&Bs[kk][tx * 4];
            float av[4] = {a4.x, a4.y, a4.z, a4.w};
            float bv[4] = {b4.x, b4.y, b4.z, b4.w};
            #pragma unroll
            for (int i = 0; i < 4; ++i)
                #pragma unroll
                for (int j = 0; j < 4; ++j)
                    acc[i][j] += av[i] * bv[j];
        }
        __syncthreads();
    }

    #pragma unroll
    for (int i = 0; i < 4; ++i) {
        int r = m0 + ty * 4 + i;
        #pragma unroll
        for (int j = 0; j < 4; ++j) {
            int cc = n0 + tx * 4 + j;
            float v = alpha * acc[i][j];
            if (BIAS) v += bias[cc];
            long off = (long)r * ldc + cc;
            if (ACC) C[off] += v; else C[off] = v;
        }
    }
}

// ---------------- row softmax (optional int mask; mask==0 -> excluded) --------
__global__ void __launch_bounds__(256) softmax_k(
    const float* __restrict__ in, float* __restrict__ out,
    const int* __restrict__ mask, int len, int maskld)
{
    int t = blockIdx.x;
    long rowoff = ((long)blockIdx.y * gridDim.x + t) * (long)len;
    const float* r = in + rowoff;
    float* o = out + rowoff;
    const int* mr = mask ? (mask + (long)t * maskld) : nullptr;

    __shared__ float sd[256];
    int tid = threadIdx.x;

    float m = -INFINITY;
    for (int i = tid; i < len; i += 256) {
        if (mr && mr[i] == 0) continue;
        m = fmaxf(m, r[i]);
    }
    sd[tid] = m; __syncthreads();
    for (int s = 128; s > 0; s >>= 1) {
        if (tid < s) sd[tid] = fmaxf(sd[tid], sd[tid + s]);
        __syncthreads();
    }
    m = sd[0];
    __syncthreads();

    float sum = 0.0f;
    for (int i = tid; i < len; i += 256) {
        if (mr && mr[i] == 0) continue;
        sum += __expf(r[i] - m);
    }
    sd[tid] = sum; __syncthreads();
    for (int s = 128; s > 0; s >>= 1) {
        if (tid < s) sd[tid] += sd[tid + s];
        __syncthreads();
    }
    float inv = 1.0f / sd[0];

    for (int i = tid; i < len; i += 256) {
        float v = (mr && mr[i] == 0) ? 0.0f : __expf(r[i] - m) * inv;
        o[i] = v;
    }
}

// ---------------- gate combine: t3 = sig(t1)*cval + sig(t2)*sval --------------
__global__ void __launch_bounds__(256) gate_combine_k(
    const float* __restrict__ gs, const float* __restrict__ gc,
    const float* __restrict__ cval, const float* __restrict__ sval,
    float* __restrict__ outv, int n)
{
    int i = blockIdx.x * 256 + threadIdx.x;
    if (i < n) {
        float a = 1.0f / (1.0f + __expf(-gs[i]));
        float b = 1.0f / (1.0f + __expf(-gc[i]));
        outv[i] = a * cval[i] + b * sval[i];
    }
}

// ------------------------------------------------------------------------------
extern "C" void kernel_launch(void* const* d_in, const int* in_sizes, int n_in,
                              void* d_out, int out_size)
{
    const float* x       = (const float*)d_in[0];   // [2,2048,512]
    const float* y       = (const float*)d_in[1];   // [2,512,512]
    const int*   mask    = (const int*)  d_in[2];   // [1,1,2048,2048]
    const float* Wqkv_x  = (const float*)d_in[3];   // [512,1536]
    const float* bqkv_x  = (const float*)d_in[4];
    const float* Wqkv_y  = (const float*)d_in[5];
    const float* bqkv_y  = (const float*)d_in[6];
    const float* Wgs     = (const float*)d_in[7];
    const float* bgs     = (const float*)d_in[8];
    const float* Wgc     = (const float*)d_in[9];
    const float* bgc     = (const float*)d_in[10];
    const float* Wp      = (const float*)d_in[11];
    const float* bp      = (const float*)d_in[12];
    float* out = (float*)d_out;

    float *qkvx, *qkvy, *cx2y, *px2y, *cy2x, *big, *cval, *sval, *t1, *t2, *t3;
    cudaGetSymbolAddress((void**)&qkvx, g_qkv_x);
    cudaGetSymbolAddress((void**)&qkvy, g_qkv_y);
    cudaGetSymbolAddress((void**)&cx2y, g_catt_x2y);
    cudaGetSymbolAddress((void**)&px2y, g_p_x2y);
    cudaGetSymbolAddress((void**)&cy2x, g_catt_y2x);
    cudaGetSymbolAddress((void**)&big,  g_big);
    cudaGetSymbolAddress((void**)&cval, g_cval);
    cudaGetSymbolAddress((void**)&sval, g_sval);
    cudaGetSymbolAddress((void**)&t1,   g_t1);
    cudaGetSymbolAddress((void**)&t2,   g_t2);
    cudaGetSymbolAddress((void**)&t3,   g_t3);

    dim3 blk(256);
    const int BH = BATCH * HH;

    // 1) qkv_x = x @ Wqkv_x + b   [4096,1536]
    gemm_k<false,false,true><<<dim3(3*CC/BN, BATCH*TT/BM, 1), blk>>>(
        x, Wqkv_x, qkvx, bqkv_x, BATCH*TT, 3*CC, CC,
        CC, 3*CC, 3*CC, 0,0,0,0,0,0, 1, 1.0f);

    // 2) qkv_y = y @ Wqkv_y + b   [1024,1536]
    gemm_k<false,false,true><<<dim3(3*CC/BN, BATCH*MM/BM, 1), blk>>>(
        y, Wqkv_y, qkvy, bqkv_y, BATCH*MM, 3*CC, CC,
        CC, 3*CC, 3*CC, 0,0,0,0,0,0, 1, 1.0f);

    // 3) catt_x2y[b,h] = q_x @ k_y^T * SCALE   [T,M], K=64
    gemm_k<true,false,false><<<dim3(MM/BN, TT/BM, BH), blk>>>(
        qkvx, qkvy + CC, cx2y, nullptr, TT, MM, DD,
        3*CC, 3*CC, MM,
        (long)TT*3*CC, DD, (long)MM*3*CC, DD,
        (long)HH*TT*MM, (long)TT*MM, HH, SCALE);

    // 4) catt_y2x[b,h] = q_y @ k_x^T * SCALE   [M,T], K=64
    gemm_k<true,false,false><<<dim3(TT/BN, MM/BM, BH), blk>>>(
        qkvy, qkvx + CC, cy2x, nullptr, MM, TT, DD,
        3*CC, 3*CC, TT,
        (long)MM*3*CC, DD, (long)TT*3*CC, DD,
        (long)HH*MM*TT, (long)MM*TT, HH, SCALE);

    // 5) p_x2y = softmax(catt_x2y) over M
    softmax_k<<<dim3(TT, BH), blk>>>(cx2y, px2y, nullptr, MM, 0);

    // 6) cval = p_x2y @ v_y   [T,64], K=512
    gemm_k<false,false,false><<<dim3(DD/BN, TT/BM, BH), blk>>>(
        px2y, qkvy + 2*CC, cval, nullptr, TT, DD, MM,
        MM, 3*CC, CC,
        (long)HH*TT*MM, (long)TT*MM, (long)MM*3*CC, DD,
        (long)TT*CC, DD, HH, 1.0f);

    // 7) prod = catt_x2y @ catt_y2x * SCALE   [T,T], K=512  (dominant GEMM)
    gemm_k<false,false,false><<<dim3(TT/BN, TT/BM, BH), blk>>>(
        cx2y, cy2x, big, nullptr, TT, TT, MM,
        MM, TT, TT,
        (long)HH*TT*MM, (long)TT*MM, (long)HH*MM*TT, (long)MM*TT,
        (long)HH*TT*TT, (long)TT*TT, HH, SCALE);

    // 8) masked softmax of prod (in place)
    softmax_k<<<dim3(TT, BH), blk>>>(big, big, mask, TT, TT);

    // 9) cval += softmax(prod) @ v_x   [T,64], K=2048
    gemm_k<false,true,false><<<dim3(DD/BN, TT/BM, BH), blk>>>(
        big, qkvx + 2*CC, cval, nullptr, TT, DD, TT,
        TT, 3*CC, CC,
        (long)HH*TT*TT, (long)TT*TT, (long)TT*3*CC, DD,
        (long)TT*CC, DD, HH, 1.0f);

    // 10) satt = q_x @ k_x^T * SCALE  [T,T], K=64  (into big, reused)
    gemm_k<true,false,false><<<dim3(TT/BN, TT/BM, BH), blk>>>(
        qkvx, qkvx + CC, big, nullptr, TT, TT, DD,
        3*CC, 3*CC, TT,
        (long)TT*3*CC, DD, (long)TT*3*CC, DD,
        (long)HH*TT*TT, (long)TT*TT, HH, SCALE);

    // 11) masked softmax (in place)
    softmax_k<<<dim3(TT, BH), blk>>>(big, big, mask, TT, TT);

    // 12) sval = softmax(satt) @ v_x
    gemm_k<false,false,false><<<dim3(DD/BN, TT/BM, BH), blk>>>(
        big, qkvx + 2*CC, sval, nullptr, TT, DD, TT,
        TT, 3*CC, CC,
        (long)HH*TT*TT, (long)TT*TT, (long)TT*3*CC, DD,
        (long)TT*CC, DD, HH, 1.0f);

    // 13) t1 = sval @ Wgs + bgs
    gemm_k<false,false,true><<<dim3(CC/BN, BATCH*TT/BM, 1), blk>>>(
        sval, Wgs, t1, bgs, BATCH*TT, CC, CC,
        CC, CC, CC, 0,0,0,0,0,0, 1, 1.0f);

    // 14) t2 = cval @ Wgc + bgc
    gemm_k<false,false,true><<<dim3(CC/BN, BATCH*TT/BM, 1), blk>>>(
        cval, Wgc, t2, bgc, BATCH*TT, CC, CC,
        CC, CC, CC, 0,0,0,0,0,0, 1, 1.0f);

    // 15) t3 = sigmoid(t1)*cval + sigmoid(t2)*sval
    {
        int n = BATCH * TT * CC;
        gate_combine_k<<<(n + 255) / 256, blk>>>(t1, t2, cval, sval, t3, n);
    }

    // 16) out = t3 @ Wp + bp
    gemm_k<false,false,true><<<dim3(CC/BN, BATCH*TT/BM, 1), blk>>>(
        t3, Wp, out, bp, BATCH*TT, CC, CC,
        CC, CC, CC, 0,0,0,0,0,0, 1, 1.0f);
}

// round 5
// speedup vs baseline: 4.2040x; 4.2040x over previous
#include <cuda_runtime.h>
#include <cuda_bf16.h>
#include <cstdint>
#include <math.h>

#define BBv 2
#define Tv 2048
#define Mv 512
#define Cv 512
#define Hv 8
#define Dv 64
#define BHv 16
#define SCL 0.125f
typedef __nv_bfloat16 bf;

// ---------- bf16 pair pool offsets (elements) ----------
constexpr long oXB   = 0;
constexpr long oYB   = oXB   + (long)BBv*Tv*Cv;
constexpr long oWQX  = oYB   + (long)BBv*Mv*Cv;
constexpr long oWQY  = oWQX  + (long)Cv*3*Cv;
constexpr long oWGS  = oWQY  + (long)Cv*3*Cv;
constexpr long oWGC  = oWGS  + (long)Cv*Cv;
constexpr long oWP   = oWGC  + (long)Cv*Cv;
constexpr long oQKVX = oWP   + (long)Cv*Cv;
constexpr long oQKVY = oQKVX + (long)BBv*Tv*3*Cv;
constexpr long oCX   = oQKVY + (long)BBv*Mv*3*Cv;
constexpr long oCY   = oCX   + (long)BHv*Tv*Mv;
constexpr long oPX   = oCY   + (long)BHv*Tv*Mv;
constexpr long oPRB  = oPX   + (long)BHv*Tv*Mv;
constexpr long oVXT  = oPRB  + (long)BHv*Tv*Tv;
constexpr long oVYT  = oVXT  + (long)BHv*Dv*Tv;
constexpr long oSV   = oVYT  + (long)BHv*Dv*Mv;
constexpr long oCV   = oSV   + (long)BBv*Tv*Cv;
constexpr long oT3   = oCV   + (long)BBv*Tv*Cv;
constexpr long NBF   = oT3   + (long)BBv*Tv*Cv;
// ---------- fp32 pool ----------
constexpr long fCX = 0;
constexpr long fBG = fCX + (long)BHv*Tv*Mv;
constexpr long fC1 = fBG + (long)BHv*Tv*Tv;
constexpr long fC2 = fC1 + (long)BBv*Tv*Cv;
constexpr long fCV = fC2 + (long)BBv*Tv*Cv;
constexpr long fSV = fCV + (long)BBv*Tv*Cv;
constexpr long fT1 = fSV + (long)BBv*Tv*Cv;
constexpr long fT2 = fT1 + (long)BBv*Tv*Cv;
constexpr long NF_  = fT2 + (long)BBv*Tv*Cv;

__device__ bf    g_h[NBF];
__device__ bf    g_l[NBF];
__device__ float g_f[NF_];

// ---------- warp MMA helpers ----------
__device__ __forceinline__ uint32_t smem_u32(const void* p) {
    uint32_t a;
    asm("{ .reg .u64 t; cvta.to.shared.u64 t, %1; cvt.u32.u64 %0, t; }" : "=r"(a) : "l"(p));
    return a;
}
#define LDM4(r, addr) asm volatile( \
    "ldmatrix.sync.aligned.m8n8.x4.shared.b16 {%0,%1,%2,%3}, [%4];" \
    : "=r"((r)[0]), "=r"((r)[1]), "=r"((r)[2]), "=r"((r)[3]) : "r"(addr))
#define MMA(c, a, b) asm volatile( \
    "mma.sync.aligned.m16n8k16.row.col.f32.bf16.bf16.f32 " \
    "{%0,%1,%2,%3}, {%4,%5,%6,%7}, {%8,%9}, {%0,%1,%2,%3};" \
    : "+f"((c)[0]), "+f"((c)[1]), "+f"((c)[2]), "+f"((c)[3]) \
    : "r"((a)[0]), "r"((a)[1]), "r"((a)[2]), "r"((a)[3]), "r"((b)[0]), "r"((b)[1]))

// ---------- HMMA split-bf16 GEMM: C = alpha*(A@B^T) (+bias) -------------------
// A:[M,K] K-major hi/lo, B:[N,K] K-major hi/lo. Block tile 128 x TN, 8 warps.
template<int TN, bool F32O, bool PO, bool BIAS, bool SKIP, bool CK>
__global__ void __launch_bounds__(256) hg(
    const bf* __restrict__ Ah, const bf* __restrict__ Al, int lda, long sAb, long sAh_,
    const bf* __restrict__ Bh, const bf* __restrict__ Bl, int ldb, long sBb, long sBh_,
    float* __restrict__ C, bf* __restrict__ Ch, bf* __restrict__ Cl, int ldc, long sCb, long sCh_,
    const float* __restrict__ bias, int K, int Hn, float alpha)
{
    constexpr int NFRAG = TN / 16;    // n-frags per warp (warp covers TN/2 cols)
    int m0 = blockIdx.y * 128, n0 = blockIdx.x * TN;
    if (SKIP && n0 >= m0 + 128) return;

    int z = blockIdx.z, bb = z / Hn, hh = z - bb * Hn;
    const bf* pAh = Ah + bb * sAb + hh * sAh_;
    const bf* pAl = Al + bb * sAb + hh * sAh_;
    const bf* pBh = Bh + bb * sBb + hh * sBh_;
    const bf* pBl = Bl + bb * sBb + hh * sBh_;
    long co = bb * sCb + hh * sCh_;

    __shared__ bf sA[2][128][40];
    __shared__ bf sB[2][TN][40];
    uint32_t baseA = smem_u32(&sA[0][0][0]);
    uint32_t baseB = smem_u32(&sB[0][0][0]);

    int tid = threadIdx.x, lane = tid & 31, wid = tid >> 5;
    int wm = (wid & 3) * 32, wn = (wid >> 2) * (TN / 2);

    float acc[2][NFRAG][4];
    #pragma unroll
    for (int i = 0; i < 2; ++i)
        #pragma unroll
        for (int j = 0; j < NFRAG; ++j)
            #pragma unroll
            for (int q = 0; q < 4; ++q) acc[i][j][q] = 0.f;

    int kst = K >> 5;
    if (CK) { int lim = (m0 >> 5) + 4; if (lim < kst) kst = lim; }

    // precomputed ldmatrix lane addressing
    int aRow = (lane & 15), aK = (lane >> 4) * 8;
    int bRow = (lane & 7) + ((lane >> 4) & 1) * 8, bK = ((lane >> 3) & 1) * 8;

    for (int s = 0; s < kst; ++s) {
        int k0 = s << 5;
        #pragma unroll
        for (int i = 0; i < 2; ++i) {
            int q = tid + i * 256, r = q >> 2, sg = (q & 3) * 8;
            long go = (long)(m0 + r) * lda + k0 + sg;
            *(uint4*)&sA[0][r][sg] = *(const uint4*)(pAh + go);
            *(uint4*)&sA[1][r][sg] = *(const uint4*)(pAl + go);
        }
        #pragma unroll
        for (int i = 0; i < TN / 64; ++i) {
            int q = tid + i * 256, r = q >> 2, sg = (q & 3) * 8;
            long go = (long)(n0 + r) * ldb + k0 + sg;
            *(uint4*)&sB[0][r][sg] = *(const uint4*)(pBh + go);
            *(uint4*)&sB[1][r][sg] = *(const uint4*)(pBl + go);
        }
        __syncthreads();

        #pragma unroll
        for (int kk = 0; kk < 2; ++kk) {
            uint32_t ah[2][4], al[2][4];
            #pragma unroll
            for (int mf = 0; mf < 2; ++mf) {
                uint32_t off = (uint32_t)((wm + mf * 16 + aRow) * 40 + kk * 16 + aK) * 2;
                LDM4(ah[mf], baseA + off);
                LDM4(al[mf], baseA + 128 * 40 * 2 + off);
            }
            uint32_t bh[NFRAG][2], bl[NFRAG][2];
            #pragma unroll
            for (int np = 0; np < NFRAG / 2; ++np) {
                uint32_t off = (uint32_t)((wn + np * 16 + bRow) * 40 + kk * 16 + bK) * 2;
                uint32_t t[4];
                LDM4(t, baseB + off);
                bh[np*2][0] = t[0]; bh[np*2][1] = t[1]; bh[np*2+1][0] = t[2]; bh[np*2+1][1] = t[3];
                LDM4(t, baseB + TN * 40 * 2 + off);
                bl[np*2][0] = t[0]; bl[np*2][1] = t[1]; bl[np*2+1][0] = t[2]; bl[np*2+1][1] = t[3];
            }
            #pragma unroll
            for (int mf = 0; mf < 2; ++mf)
                #pragma unroll
                for (int nf = 0; nf < NFRAG; ++nf) {
                    MMA(acc[mf][nf], ah[mf], bh[nf]);
                    MMA(acc[mf][nf], ah[mf], bl[nf]);
                    MMA(acc[mf][nf], al[mf], bh[nf]);
                }
        }
        __syncthreads();
    }

    // epilogue: fragment-direct stores
    int rb = m0 + wm + (lane >> 2);
    int cb = n0 + wn + (lane & 3) * 2;
    #pragma unroll
    for (int mf = 0; mf < 2; ++mf)
        #pragma unroll
        for (int half = 0; half < 2; ++half) {
            long row = rb + mf * 16 + half * 8;
            #pragma unroll
            for (int nf = 0; nf < NFRAG; ++nf) {
                int cc = cb + nf * 8;
                float v0 = alpha * acc[mf][nf][half * 2 + 0];
                float v1 = alpha * acc[mf][nf][half * 2 + 1];
                if (BIAS) { v0 += bias[cc]; v1 += bias[cc + 1]; }
                long base = co + row * (long)ldc + cc;
                if (F32O) { C[base] = v0; C[base + 1] = v1; }
                if (PO) {
                    bf h0 = __float2bfloat16(v0), h1 = __float2bfloat16(v1);
                    __nv_bfloat162 hp; hp.x = h0; hp.y = h1;
                    __nv_bfloat162 lp;
                    lp.x = __float2bfloat16(v0 - __bfloat162float(h0));
                    lp.y = __float2bfloat16(v1 - __bfloat162float(h1));
                    *reinterpret_cast<__nv_bfloat162*>(Ch + base) = hp;
                    *reinterpret_cast<__nv_bfloat162*>(Cl + base) = lp;
                }
            }
        }
}

// ---------- softmax: fp32 in -> bf16 hi/lo probs (optional causal) ----------
template<bool CAUSAL>
__global__ void __launch_bounds__(256) sm_k(const float* __restrict__ in, bf* __restrict__ oh,
                                            bf* __restrict__ ol, int len)
{
    int t = blockIdx.x, z = blockIdx.y, tid = threadIdx.x;
    long base = ((long)z * Tv + t) * (long)len;
    int eff = CAUSAL ? t + 1 : len;
    int fill = CAUSAL ? (((t >> 7) + 1) << 7) : len;
    __shared__ float sd[256];
    float m = -INFINITY;
    for (int i = tid; i < eff; i += 256) m = fmaxf(m, in[base + i]);
    sd[tid] = m; __syncthreads();
    for (int s = 128; s > 0; s >>= 1) { if (tid < s) sd[tid] = fmaxf(sd[tid], sd[tid+s]); __syncthreads(); }
    m = sd[0]; __syncthreads();
    float sum = 0.f;
    for (int i = tid; i < eff; i += 256) sum += __expf(in[base + i] - m);
    sd[tid] = sum; __syncthreads();
    for (int s = 128; s > 0; s >>= 1) { if (tid < s) sd[tid] += sd[tid+s]; __syncthreads(); }
    float inv = 1.0f / sd[0];
    for (int i = tid; i < fill; i += 256) {
        float p = (i < eff) ? __expf(in[base + i] - m) * inv : 0.f;
        bf h = __float2bfloat16(p);
        oh[base + i] = h;
        ol[base + i] = __float2bfloat16(p - __bfloat162float(h));
    }
}

// ---------- small utility kernels ----------
__global__ void split_k(const float* __restrict__ in, bf* __restrict__ oh, bf* __restrict__ ol, long n) {
    long i = (long)blockIdx.x * 256 + threadIdx.x;
    if (i < n) {
        float v = in[i]; bf h = __float2bfloat16(v);
        oh[i] = h; ol[i] = __float2bfloat16(v - __bfloat162float(h));
    }
}
__global__ void splitT_k(const float* __restrict__ in, bf* __restrict__ oh, bf* __restrict__ ol, int Kd, int Nd) {
    long i = (long)blockIdx.x * 256 + threadIdx.x;
    if (i < (long)Kd * Nd) {
        int n = (int)(i / Kd), k = (int)(i % Kd);
        float v = in[(long)k * Nd + n]; bf h = __float2bfloat16(v);
        oh[i] = h; ol[i] = __float2bfloat16(v - __bfloat162float(h));
    }
}
__global__ void vT_k(const bf* __restrict__ ih, const bf* __restrict__ il,
                     bf* __restrict__ oh, bf* __restrict__ ol, int L) {
    int z = blockIdx.y, b = z / Hv, h = z % Hv;
    long iof = (long)b * L * 3 * Cv + (long)h * Dv + 2 * Cv;
    long oof = (long)z * Dv * L;
    int idx = blockIdx.x * 256 + threadIdx.x;
    int d = idx / L, l = idx % L;
    long ii = iof + (long)l * 3 * Cv + d;
    oh[oof + idx] = ih[ii]; ol[oof + idx] = il[ii];
}
__global__ void add_k(const float* __restrict__ a, const float* __restrict__ b,
                      float* __restrict__ of, bf* __restrict__ oh, bf* __restrict__ ol, long n) {
    long i = (long)blockIdx.x * 256 + threadIdx.x;
    if (i < n) {
        float v = a[i] + b[i]; of[i] = v;
        bf h = __float2bfloat16(v);
        oh[i] = h; ol[i] = __float2bfloat16(v - __bfloat162float(h));
    }
}
__global__ void gate_k(const float* __restrict__ t1, const float* __restrict__ t2,
                       const float* __restrict__ cv, const float* __restrict__ sv,
                       bf* __restrict__ oh, bf* __restrict__ ol, long n) {
    long i = (long)blockIdx.x * 256 + threadIdx.x;
    if (i < n) {
        float g1 = 1.f / (1.f + __expf(-t1[i]));
        float g2 = 1.f / (1.f + __expf(-t2[i]));
        float v = g1 * cv[i] + g2 * sv[i];
        bf h = __float2bfloat16(v);
        oh[i] = h; ol[i] = __float2bfloat16(v - __bfloat162float(h));
    }
}

// ------------------------------------------------------------------------------
extern "C" void kernel_launch(void* const* d_in, const int* in_sizes, int n_in,
                              void* d_out, int out_size)
{
    const float* x      = (const float*)d_in[0];
    const float* y      = (const float*)d_in[1];
    const float* Wqkv_x = (const float*)d_in[3];
    const float* bqkv_x = (const float*)d_in[4];
    const float* Wqkv_y = (const float*)d_in[5];
    const float* bqkv_y = (const float*)d_in[6];
    const float* Wgs    = (const float*)d_in[7];
    const float* bgs    = (const float*)d_in[8];
    const float* Wgc    = (const float*)d_in[9];
    const float* bgc    = (const float*)d_in[10];
    const float* Wp     = (const float*)d_in[11];
    const float* bp     = (const float*)d_in[12];
    float* out = (float*)d_out;

    bf *gh, *gl; float* gf;
    cudaGetSymbolAddress((void**)&gh, g_h);
    cudaGetSymbolAddress((void**)&gl, g_l);
    cudaGetSymbolAddress((void**)&gf, g_f);

    dim3 blk(256);
    long nTC = (long)BBv * Tv * Cv;

    // input / weight splits
    split_k<<<(unsigned)((nTC + 255) / 256), blk>>>(x, gh + oXB, gl + oXB, nTC);
    split_k<<<(unsigned)((BBv*Mv*Cv + 255) / 256), blk>>>(y, gh + oYB, gl + oYB, (long)BBv*Mv*Cv);
    splitT_k<<<(unsigned)((Cv*3*Cv + 255) / 256), blk>>>(Wqkv_x, gh + oWQX, gl + oWQX, Cv, 3*Cv);
    splitT_k<<<(unsigned)((Cv*3*Cv + 255) / 256), blk>>>(Wqkv_y, gh + oWQY, gl + oWQY, Cv, 3*Cv);
    splitT_k<<<(unsigned)((Cv*Cv + 255) / 256), blk>>>(Wgs, gh + oWGS, gl + oWGS, Cv, Cv);
    splitT_k<<<(unsigned)((Cv*Cv + 255) / 256), blk>>>(Wgc, gh + oWGC, gl + oWGC, Cv, Cv);
    splitT_k<<<(unsigned)((Cv*Cv + 255) / 256), blk>>>(Wp,  gh + oWP,  gl + oWP,  Cv, Cv);

    // qkv projections (pair out)
    hg<128,false,true,true,false,false><<<dim3(12,32,1), blk>>>(
        gh+oXB, gl+oXB, Cv, 0,0, gh+oWQX, gl+oWQX, Cv, 0,0,
        nullptr, gh+oQKVX, gl+oQKVX, 3*Cv, 0,0, bqkv_x, Cv, 1, 1.0f);
    hg<128,false,true,true,false,false><<<dim3(12,8,1), blk>>>(
        gh+oYB, gl+oYB, Cv, 0,0, gh+oWQY, gl+oWQY, Cv, 0,0,
        nullptr, gh+oQKVY, gl+oQKVY, 3*Cv, 0,0, bqkv_y, Cv, 1, 1.0f);

    // v transposes
    vT_k<<<dim3(Dv*Tv/256, BHv), blk>>>(gh+oQKVX, gl+oQKVX, gh+oVXT, gl+oVXT, Tv);
    vT_k<<<dim3(Dv*Mv/256, BHv), blk>>>(gh+oQKVY, gl+oQKVY, gh+oVYT, gl+oVYT, Mv);

    // catt_x2y = q_x @ k_y^T * SCL  (f32 + pair)
    hg<128,true,true,false,false,false><<<dim3(4,16,16), blk>>>(
        gh+oQKVX, gl+oQKVX, 3*Cv, (long)Tv*3*Cv, (long)Dv,
        gh+oQKVY+Cv, gl+oQKVY+Cv, 3*Cv, (long)Mv*3*Cv, (long)Dv,
        gf+fCX, gh+oCX, gl+oCX, Mv, (long)Hv*Tv*Mv, (long)Tv*Mv, nullptr, Dv, Hv, SCL);

    // catt_y2x^T = k_x @ q_y^T * SCL  (pair only)
    hg<128,false,true,false,false,false><<<dim3(4,16,16), blk>>>(
        gh+oQKVX+Cv, gl+oQKVX+Cv, 3*Cv, (long)Tv*3*Cv, (long)Dv,
        gh+oQKVY, gl+oQKVY, 3*Cv, (long)Mv*3*Cv, (long)Dv,
        nullptr, gh+oCY, gl+oCY, Mv, (long)Hv*Tv*Mv, (long)Tv*Mv, nullptr, Dv, Hv, SCL);

    // p_x2y = softmax(catt_x2y)
    sm_k<false><<<dim3(Tv, BHv), blk>>>(gf+fCX, gh+oPX, gl+oPX, Mv);

    // cval1 = p_x2y @ v_y
    hg<64,true,false,false,false,false><<<dim3(1,16,16), blk>>>(
        gh+oPX, gl+oPX, Mv, (long)Hv*Tv*Mv, (long)Tv*Mv,
        gh+oVYT, gl+oVYT, Mv, (long)Hv*Dv*Mv, (long)Dv*Mv,
        gf+fC1, nullptr, nullptr, Cv, (long)Tv*Cv, (long)Dv, nullptr, Mv, Hv, 1.0f);

    // prod = catt_x2y @ catt_y2x * SCL  (causal tile-skip)
    hg<128,true,false,false,true,false><<<dim3(16,16,16), blk>>>(
        gh+oCX, gl+oCX, Mv, (long)Hv*Tv*Mv, (long)Tv*Mv,
        gh+oCY, gl+oCY, Mv, (long)Hv*Tv*Mv, (long)Tv*Mv,
        gf+fBG, nullptr, nullptr, Tv, (long)Hv*Tv*Tv, (long)Tv*Tv, nullptr, Mv, Hv, SCL);

    // causal softmax -> probs pair
    sm_k<true><<<dim3(Tv, BHv), blk>>>(gf+fBG, gh+oPRB, gl+oPRB, Tv);

    // cval2 = probs @ v_x  (causal K-trunc)
    hg<64,true,false,false,false,true><<<dim3(1,16,16), blk>>>(
        gh+oPRB, gl+oPRB, Tv, (long)Hv*Tv*Tv, (long)Tv*Tv,
        gh+oVXT, gl+oVXT, Tv, (long)Hv*Dv*Tv, (long)Dv*Tv,
        gf+fC2, nullptr, nullptr, Cv, (long)Tv*Cv, (long)Dv, nullptr, Tv, Hv, 1.0f);

    // satt = q_x @ k_x^T * SCL  (causal tile-skip)
    hg<128,true,false,false,true,false><<<dim3(16,16,16), blk>>>(
        gh+oQKVX, gl+oQKVX, 3*Cv, (long)Tv*3*Cv, (long)Dv,
        gh+oQKVX+Cv, gl+oQKVX+Cv, 3*Cv, (long)Tv*3*Cv, (long)Dv,
        gf+fBG, nullptr, nullptr, Tv, (long)Hv*Tv*Tv, (long)Tv*Tv, nullptr, Dv, Hv, SCL);

    sm_k<true><<<dim3(Tv, BHv), blk>>>(gf+fBG, gh+oPRB, gl+oPRB, Tv);

    // sval = probs @ v_x  (f32 + pair)
    hg<64,true,true,false,false,true><<<dim3(1,16,16), blk>>>(
        gh+oPRB, gl+oPRB, Tv, (long)Hv*Tv*Tv, (long)Tv*Tv,
        gh+oVXT, gl+oVXT, Tv, (long)Hv*Dv*Tv, (long)Dv*Tv,
        gf+fSV, gh+oSV, gl+oSV, Cv, (long)Tv*Cv, (long)Dv, nullptr, Tv, Hv, 1.0f);

    // cval = cval1 + cval2 (f32 + pair)
    add_k<<<(unsigned)((nTC + 255) / 256), blk>>>(gf+fC1, gf+fC2, gf+fCV, gh+oCV, gl+oCV, nTC);

    // gates
    hg<128,true,false,true,false,false><<<dim3(4,32,1), blk>>>(
        gh+oSV, gl+oSV, Cv, 0,0, gh+oWGS, gl+oWGS, Cv, 0,0,
        gf+fT1, nullptr, nullptr, Cv, 0,0, bgs, Cv, 1, 1.0f);
    hg<128,true,false,true,false,false><<<dim3(4,32,1), blk>>>(
        gh+oCV, gl+oCV, Cv, 0,0, gh+oWGC, gl+oWGC, Cv, 0,0,
        gf+fT2, nullptr, nullptr, Cv, 0,0, bgc, Cv, 1, 1.0f);

    gate_k<<<(unsigned)((nTC + 255) / 256), blk>>>(gf+fT1, gf+fT2, gf+fCV, gf+fSV, gh+oT3, gl+oT3, nTC);

    // out = t3 @ Wp + bp
    hg<128,true,false,true,false,false><<<dim3(4,32,1), blk>>>(
        gh+oT3, gl+oT3, Cv, 0,0, gh+oWP, gl+oWP, Cv, 0,0,
        out, nullptr, nullptr, Cv, 0,0, bp, Cv, 1, 1.0f);
}

// round 7
// speedup vs baseline: 5.1911x; 1.2348x over previous
#include <cuda_runtime.h>
#include <cuda_bf16.h>
#include <cstdint>
#include <math.h>

#define BBv 2
#define Tv 2048
#define Mv 512
#define Cv 512
#define Hv 8
#define Dv 64
#define BHv 16
#define SCL 0.125f
typedef __nv_bfloat16 bf;

// ---------- bf16 pair pool offsets (elements) ----------
constexpr long oXB   = 0;
constexpr long oYB   = oXB   + (long)BBv*Tv*Cv;
constexpr long oWQX  = oYB   + (long)BBv*Mv*Cv;
constexpr long oWQY  = oWQX  + (long)Cv*3*Cv;
constexpr long oWGS  = oWQY  + (long)Cv*3*Cv;
constexpr long oWGC  = oWGS  + (long)Cv*Cv;
constexpr long oWP   = oWGC  + (long)Cv*Cv;
constexpr long oQKVX = oWP   + (long)Cv*Cv;
constexpr long oQKVY = oQKVX + (long)BBv*Tv*3*Cv;
constexpr long oQXG  = oQKVY + (long)BBv*Mv*3*Cv;     // qxG pair [BH,T,64]
constexpr long oGT   = oQXG  + (long)BHv*Tv*Dv;       // G^T pair [BH,64,64]
constexpr long oPX   = oGT   + (long)BHv*Dv*Dv;
constexpr long oPRB  = oPX   + (long)BHv*Tv*Mv;
constexpr long oVXT  = oPRB  + (long)BHv*Tv*Tv;
constexpr long oVYT  = oVXT  + (long)BHv*Dv*Tv;
constexpr long oSV   = oVYT  + (long)BHv*Dv*Mv;
constexpr long oCV   = oSV   + (long)BBv*Tv*Cv;
constexpr long oT3   = oCV   + (long)BBv*Tv*Cv;
constexpr long NBF   = oT3   + (long)BBv*Tv*Cv;
// ---------- fp32 pool ----------
constexpr long fCX = 0;
constexpr long fBG = fCX + (long)BHv*Tv*Mv;
constexpr long fC1 = fBG + (long)BHv*Tv*Tv;
constexpr long fC2 = fC1 + (long)BBv*Tv*Cv;
constexpr long fCV = fC2 + (long)BBv*Tv*Cv;
constexpr long fSV = fCV + (long)BBv*Tv*Cv;
constexpr long fT1 = fSV + (long)BBv*Tv*Cv;
constexpr long fT2 = fT1 + (long)BBv*Tv*Cv;
constexpr long NF_  = fT2 + (long)BBv*Tv*Cv;

__device__ bf    g_h[NBF];
__device__ bf    g_l[NBF];
__device__ float g_f[NF_];

// ---------- warp MMA helpers ----------
__device__ __forceinline__ uint32_t smem_u32(const void* p) {
    uint32_t a;
    asm("{ .reg .u64 t; cvta.to.shared.u64 t, %1; cvt.u32.u64 %0, t; }" : "=r"(a) : "l"(p));
    return a;
}
#define LDM4(r, addr) asm volatile( \
    "ldmatrix.sync.aligned.m8n8.x4.shared.b16 {%0,%1,%2,%3}, [%4];" \
    : "=r"((r)[0]), "=r"((r)[1]), "=r"((r)[2]), "=r"((r)[3]) : "r"(addr))
#define MMA(c, a, b) asm volatile( \
    "mma.sync.aligned.m16n8k16.row.col.f32.bf16.bf16.f32 " \
    "{%0,%1,%2,%3}, {%4,%5,%6,%7}, {%8,%9}, {%0,%1,%2,%3};" \
    : "+f"((c)[0]), "+f"((c)[1]), "+f"((c)[2]), "+f"((c)[3]) \
    : "r"((a)[0]), "r"((a)[1]), "r"((a)[2]), "r"((a)[3]), "r"((b)[0]), "r"((b)[1]))

// ---------- HMMA split-bf16 GEMM: C = alpha*(A@B^T) (+bias) -------------------
template<int TN, bool F32O, bool PO, bool BIAS, bool SKIP, bool CK>
__global__ void __launch_bounds__(256) hg(
    const bf* __restrict__ Ah, const bf* __restrict__ Al, int lda, long sAb, long sAh_,
    const bf* __restrict__ Bh, const bf* __restrict__ Bl, int ldb, long sBb, long sBh_,
    float* __restrict__ C, bf* __restrict__ Ch, bf* __restrict__ Cl, int ldc, long sCb, long sCh_,
    const float* __restrict__ bias, int K, int Hn, float alpha)
{
    constexpr int NFRAG = TN / 16;
    int m0 = blockIdx.y * 128, n0 = blockIdx.x * TN;
    if (SKIP && n0 >= m0 + 128) return;

    int z = blockIdx.z, bb = z / Hn, hh = z - bb * Hn;
    const bf* pAh = Ah + bb * sAb + hh * sAh_;
    const bf* pAl = Al + bb * sAb + hh * sAh_;
    const bf* pBh = Bh + bb * sBb + hh * sBh_;
    const bf* pBl = Bl + bb * sBb + hh * sBh_;
    long co = bb * sCb + hh * sCh_;

    __shared__ bf sA[2][128][40];
    __shared__ bf sB[2][TN][40];
    uint32_t baseA = smem_u32(&sA[0][0][0]);
    uint32_t baseB = smem_u32(&sB[0][0][0]);

    int tid = threadIdx.x, lane = tid & 31, wid = tid >> 5;
    int wm = (wid & 3) * 32, wn = (wid >> 2) * (TN / 2);

    float acc[2][NFRAG][4];
    #pragma unroll
    for (int i = 0; i < 2; ++i)
        #pragma unroll
        for (int j = 0; j < NFRAG; ++j)
            #pragma unroll
            for (int q = 0; q < 4; ++q) acc[i][j][q] = 0.f;

    int kst = K >> 5;
    if (CK) { int lim = (m0 >> 5) + 4; if (lim < kst) kst = lim; }

    int aRow = (lane & 15), aK = (lane >> 4) * 8;
    int bRow = (lane & 7) + ((lane >> 4) & 1) * 8, bK = ((lane >> 3) & 1) * 8;

    for (int s = 0; s < kst; ++s) {
        int k0 = s << 5;
        #pragma unroll
        for (int i = 0; i < 2; ++i) {
            int q = tid + i * 256, r = q >> 2, sg = (q & 3) * 8;
            long go = (long)(m0 + r) * lda + k0 + sg;
            *(uint4*)&sA[0][r][sg] = *(const uint4*)(pAh + go);
            *(uint4*)&sA[1][r][sg] = *(const uint4*)(pAl + go);
        }
        #pragma unroll
        for (int i = 0; i < TN / 64; ++i) {
            int q = tid + i * 256, r = q >> 2, sg = (q & 3) * 8;
            long go = (long)(n0 + r) * ldb + k0 + sg;
            *(uint4*)&sB[0][r][sg] = *(const uint4*)(pBh + go);
            *(uint4*)&sB[1][r][sg] = *(const uint4*)(pBl + go);
        }
        __syncthreads();

        #pragma unroll
        for (int kk = 0; kk < 2; ++kk) {
            uint32_t ah[2][4], al[2][4];
            #pragma unroll
            for (int mf = 0; mf < 2; ++mf) {
                uint32_t off = (uint32_t)((wm + mf * 16 + aRow) * 40 + kk * 16 + aK) * 2;
                LDM4(ah[mf], baseA + off);
                LDM4(al[mf], baseA + 128 * 40 * 2 + off);
            }
            uint32_t bh[NFRAG][2], bl[NFRAG][2];
            #pragma unroll
            for (int np = 0; np < NFRAG / 2; ++np) {
                uint32_t off = (uint32_t)((wn + np * 16 + bRow) * 40 + kk * 16 + bK) * 2;
                uint32_t t[4];
                LDM4(t, baseB + off);
                bh[np*2][0] = t[0]; bh[np*2][1] = t[1]; bh[np*2+1][0] = t[2]; bh[np*2+1][1] = t[3];
                LDM4(t, baseB + TN * 40 * 2 + off);
                bl[np*2][0] = t[0]; bl[np*2][1] = t[1]; bl[np*2+1][0] = t[2]; bl[np*2+1][1] = t[3];
            }
            #pragma unroll
            for (int mf = 0; mf < 2; ++mf)
                #pragma unroll
                for (int nf = 0; nf < NFRAG; ++nf) {
                    MMA(acc[mf][nf], ah[mf], bh[nf]);
                    MMA(acc[mf][nf], ah[mf], bl[nf]);
                    MMA(acc[mf][nf], al[mf], bh[nf]);
                }
        }
        __syncthreads();
    }

    int rb = m0 + wm + (lane >> 2);
    int cb = n0 + wn + (lane & 3) * 2;
    #pragma unroll
    for (int mf = 0; mf < 2; ++mf)
        #pragma unroll
        for (int half = 0; half < 2; ++half) {
            long row = rb + mf * 16 + half * 8;
            #pragma unroll
            for (int nf = 0; nf < NFRAG; ++nf) {
                int cc = cb + nf * 8;
                float v0 = alpha * acc[mf][nf][half * 2 + 0];
                float v1 = alpha * acc[mf][nf][half * 2 + 1];
                if (BIAS) { v0 += bias[cc]; v1 += bias[cc + 1]; }
                long base = co + row * (long)ldc + cc;
                if (F32O) { C[base] = v0; C[base + 1] = v1; }
                if (PO) {
                    bf h0 = __float2bfloat16(v0), h1 = __float2bfloat16(v1);
                    __nv_bfloat162 hp; hp.x = h0; hp.y = h1;
                    __nv_bfloat162 lp;
                    lp.x = __float2bfloat16(v0 - __bfloat162float(h0));
                    lp.y = __float2bfloat16(v1 - __bfloat162float(h1));
                    *reinterpret_cast<__nv_bfloat162*>(Ch + base) = hp;
                    *reinterpret_cast<__nv_bfloat162*>(Cl + base) = lp;
                }
            }
        }
}

// ---------- G^T = SCL^2 * (k_y^T q_y)^T per head : [BH,64,64] bf16 pair -------
__global__ void __launch_bounds__(256) g_k(const bf* __restrict__ qh, const bf* __restrict__ ql,
                                           bf* __restrict__ goh, bf* __restrict__ gol)
{
    int z = blockIdx.x, b = z >> 3, h = z & 7;
    long kyo = (long)b * Mv * 3 * Cv + (long)h * Dv + Cv;
    long qyo = (long)b * Mv * 3 * Cv + (long)h * Dv;
    __shared__ float sky[64][65], sqy[64][65];
    int tid = threadIdx.x;
    int d2 = tid & 63, gg = tid >> 6;
    float acc[16];
    #pragma unroll
    for (int i = 0; i < 16; ++i) acc[i] = 0.f;
    for (int m0 = 0; m0 < Mv; m0 += 64) {
        #pragma unroll
        for (int i = 0; i < 16; ++i) {
            int q = tid + i * 256;
            int mm = q >> 6, dd = q & 63;
            long ik = kyo + (long)(m0 + mm) * 3 * Cv + dd;
            long iq = qyo + (long)(m0 + mm) * 3 * Cv + dd;
            sky[mm][dd] = __bfloat162float(qh[ik]) + __bfloat162float(ql[ik]);
            sqy[mm][dd] = __bfloat162float(qh[iq]) + __bfloat162float(ql[iq]);
        }
        __syncthreads();
        for (int mm = 0; mm < 64; ++mm) {
            float qv = sqy[mm][d2];
            #pragma unroll
            for (int i = 0; i < 16; ++i)
                acc[i] += sky[mm][gg * 16 + i] * qv;
        }
        __syncthreads();
    }
    long base = (long)z * 4096 + (long)d2 * 64 + gg * 16;
    #pragma unroll
    for (int i = 0; i < 16; ++i) {
        float v = acc[i] * (SCL * SCL);
        bf hh = __float2bfloat16(v);
        goh[base + i] = hh;
        gol[base + i] = __float2bfloat16(v - __bfloat162float(hh));
    }
}

// ---------- softmax: fp32 in -> bf16 hi/lo probs (optional causal) ----------
template<bool CAUSAL>
__global__ void __launch_bounds__(256) sm_k(const float* __restrict__ in, bf* __restrict__ oh,
                                            bf* __restrict__ ol, int len)
{
    int t = blockIdx.x, z = blockIdx.y, tid = threadIdx.x;
    long base = ((long)z * Tv + t) * (long)len;
    int eff = CAUSAL ? t + 1 : len;
    int fill = CAUSAL ? (((t >> 7) + 1) << 7) : len;
    __shared__ float sd[256];
    float m = -INFINITY;
    for (int i = tid; i < eff; i += 256) m = fmaxf(m, in[base + i]);
    sd[tid] = m; __syncthreads();
    for (int s = 128; s > 0; s >>= 1) { if (tid < s) sd[tid] = fmaxf(sd[tid], sd[tid+s]); __syncthreads(); }
    m = sd[0]; __syncthreads();
    float sum = 0.f;
    for (int i = tid; i < eff; i += 256) sum += __expf(in[base + i] - m);
    sd[tid] = sum; __syncthreads();
    for (int s = 128; s > 0; s >>= 1) { if (tid < s) sd[tid] += sd[tid+s]; __syncthreads(); }
    float inv = 1.0f / sd[0];
    for (int i = tid; i < fill; i += 256) {
        float p = (i < eff) ? __expf(in[base + i] - m) * inv : 0.f;
        bf h = __float2bfloat16(p);
        oh[base + i] = h;
        ol[base + i] = __float2bfloat16(p - __bfloat162float(h));
    }
}

// ---------- small utility kernels ----------
__global__ void split_k(const float* __restrict__ in, bf* __restrict__ oh, bf* __restrict__ ol, long n) {
    long i = (long)blockIdx.x * 256 + threadIdx.x;
    if (i < n) {
        float v = in[i]; bf h = __float2bfloat16(v);
        oh[i] = h; ol[i] = __float2bfloat16(v - __bfloat162float(h));
    }
}
__global__ void splitT_k(const float* __restrict__ in, bf* __restrict__ oh, bf* __restrict__ ol, int Kd, int Nd) {
    long i = (long)blockIdx.x * 256 + threadIdx.x;
    if (i < (long)Kd * Nd) {
        int n = (int)(i / Kd), k = (int)(i % Kd);
        float v = in[(long)k * Nd + n]; bf h = __float2bfloat16(v);
        oh[i] = h; ol[i] = __float2bfloat16(v - __bfloat162float(h));
    }
}
__global__ void vT_k(const bf* __restrict__ ih, const bf* __restrict__ il,
                     bf* __restrict__ oh, bf* __restrict__ ol, int L) {
    int z = blockIdx.y, b = z / Hv, h = z % Hv;
    long iof = (long)b * L * 3 * Cv + (long)h * Dv + 2 * Cv;
    long oof = (long)z * Dv * L;
    int idx = blockIdx.x * 256 + threadIdx.x;
    int d = idx / L, l = idx % L;
    long ii = iof + (long)l * 3 * Cv + d;
    oh[oof + idx] = ih[ii]; ol[oof + idx] = il[ii];
}
__global__ void add_k(const float* __restrict__ a, const float* __restrict__ b,
                      float* __restrict__ of, bf* __restrict__ oh, bf* __restrict__ ol, long n) {
    long i = (long)blockIdx.x * 256 + threadIdx.x;
    if (i < n) {
        float v = a[i] + b[i]; of[i] = v;
        bf h = __float2bfloat16(v);
        oh[i] = h; ol[i] = __float2bfloat16(v - __bfloat162float(h));
    }
}
__global__ void gate_k(const float* __restrict__ t1, const float* __restrict__ t2,
                       const float* __restrict__ cv, const float* __restrict__ sv,
                       bf* __restrict__ oh, bf* __restrict__ ol, long n) {
    long i = (long)blockIdx.x * 256 + threadIdx.x;
    if (i < n) {
        float g1 = 1.f / (1.f + __expf(-t1[i]));
        float g2 = 1.f / (1.f + __expf(-t2[i]));
        float v = g1 * cv[i] + g2 * sv[i];
        bf h = __float2bfloat16(v);
        oh[i] = h; ol[i] = __float2bfloat16(v - __bfloat162float(h));
    }
}

// ------------------------------------------------------------------------------
extern "C" void kernel_launch(void* const* d_in, const int* in_sizes, int n_in,
                              void* d_out, int out_size)
{
    const float* x      = (const float*)d_in[0];
    const float* y      = (const float*)d_in[1];
    const float* Wqkv_x = (const float*)d_in[3];
    const float* bqkv_x = (const float*)d_in[4];
    const float* Wqkv_y = (const float*)d_in[5];
    const float* bqkv_y = (const float*)d_in[6];
    const float* Wgs    = (const float*)d_in[7];
    const float* bgs    = (const float*)d_in[8];
    const float* Wgc    = (const float*)d_in[9];
    const float* bgc    = (const float*)d_in[10];
    const float* Wp     = (const float*)d_in[11];
    const float* bp     = (const float*)d_in[12];
    float* out = (float*)d_out;

    bf *gh, *gl; float* gf;
    cudaGetSymbolAddress((void**)&gh, g_h);
    cudaGetSymbolAddress((void**)&gl, g_l);
    cudaGetSymbolAddress((void**)&gf, g_f);

    dim3 blk(256);
    long nTC = (long)BBv * Tv * Cv;

    // input / weight splits
    split_k<<<(unsigned)((nTC + 255) / 256), blk>>>(x, gh + oXB, gl + oXB, nTC);
    split_k<<<(unsigned)((BBv*Mv*Cv + 255) / 256), blk>>>(y, gh + oYB, gl + oYB, (long)BBv*Mv*Cv);
    splitT_k<<<(unsigned)((Cv*3*Cv + 255) / 256), blk>>>(Wqkv_x, gh + oWQX, gl + oWQX, Cv, 3*Cv);
    splitT_k<<<(unsigned)((Cv*3*Cv + 255) / 256), blk>>>(Wqkv_y, gh + oWQY, gl + oWQY, Cv, 3*Cv);
    splitT_k<<<(unsigned)((Cv*Cv + 255) / 256), blk>>>(Wgs, gh + oWGS, gl + oWGS, Cv, Cv);
    splitT_k<<<(unsigned)((Cv*Cv + 255) / 256), blk>>>(Wgc, gh + oWGC, gl + oWGC, Cv, Cv);
    splitT_k<<<(unsigned)((Cv*Cv + 255) / 256), blk>>>(Wp,  gh + oWP,  gl + oWP,  Cv, Cv);

    // qkv projections (pair out)
    hg<128,false,true,true,false,false><<<dim3(12,32,1), blk>>>(
        gh+oXB, gl+oXB, Cv, 0,0, gh+oWQX, gl+oWQX, Cv, 0,0,
        nullptr, gh+oQKVX, gl+oQKVX, 3*Cv, 0,0, bqkv_x, Cv, 1, 1.0f);
    hg<128,false,true,true,false,false><<<dim3(12,8,1), blk>>>(
        gh+oYB, gl+oYB, Cv, 0,0, gh+oWQY, gl+oWQY, Cv, 0,0,
        nullptr, gh+oQKVY, gl+oQKVY, 3*Cv, 0,0, bqkv_y, Cv, 1, 1.0f);

    // v transposes
    vT_k<<<dim3(Dv*Tv/256, BHv), blk>>>(gh+oQKVX, gl+oQKVX, gh+oVXT, gl+oVXT, Tv);
    vT_k<<<dim3(Dv*Mv/256, BHv), blk>>>(gh+oQKVY, gl+oQKVY, gh+oVYT, gl+oVYT, Mv);

    // G^T = SCL^2 * (k_y^T @ q_y)^T  [BH,64,64]
    g_k<<<BHv, blk>>>(gh+oQKVY, gl+oQKVY, gh+oGT, gl+oGT);

    // qxG = q_x @ G  [BH,T,64]  (pair out)
    hg<64,false,true,false,false,false><<<dim3(1,16,16), blk>>>(
        gh+oQKVX, gl+oQKVX, 3*Cv, (long)Tv*3*Cv, (long)Dv,
        gh+oGT, gl+oGT, 64, (long)Hv*Dv*Dv, (long)Dv*Dv,
        nullptr, gh+oQXG, gl+oQXG, Dv, (long)Hv*Tv*Dv, (long)Tv*Dv, nullptr, Dv, Hv, 1.0f);

    // catt_x2y = q_x @ k_y^T * SCL  (f32 only, for softmax)
    hg<128,true,false,false,false,false><<<dim3(4,16,16), blk>>>(
        gh+oQKVX, gl+oQKVX, 3*Cv, (long)Tv*3*Cv, (long)Dv,
        gh+oQKVY+Cv, gl+oQKVY+Cv, 3*Cv, (long)Mv*3*Cv, (long)Dv,
        gf+fCX, nullptr, nullptr, Mv, (long)Hv*Tv*Mv, (long)Tv*Mv, nullptr, Dv, Hv, SCL);

    // p_x2y = softmax(catt_x2y)
    sm_k<false><<<dim3(Tv, BHv), blk>>>(gf+fCX, gh+oPX, gl+oPX, Mv);

    // cval1 = p_x2y @ v_y
    hg<64,true,false,false,false,false><<<dim3(1,16,16), blk>>>(
        gh+oPX, gl+oPX, Mv, (long)Hv*Tv*Mv, (long)Tv*Mv,
        gh+oVYT, gl+oVYT, Mv, (long)Hv*Dv*Mv, (long)Dv*Mv,
        gf+fC1, nullptr, nullptr, Cv, (long)Tv*Cv, (long)Dv, nullptr, Mv, Hv, 1.0f);

    // prod = (qxG) @ k_x^T * SCL   (K=64, causal tile-skip)
    hg<128,true,false,false,true,false><<<dim3(16,16,16), blk>>>(
        gh+oQXG, gl+oQXG, Dv, (long)Hv*Tv*Dv, (long)Tv*Dv,
        gh+oQKVX+Cv, gl+oQKVX+Cv, 3*Cv, (long)Tv*3*Cv, (long)Dv,
        gf+fBG, nullptr, nullptr, Tv, (long)Hv*Tv*Tv, (long)Tv*Tv, nullptr, Dv, Hv, SCL);

    // causal softmax -> probs pair
    sm_k<true><<<dim3(Tv, BHv), blk>>>(gf+fBG, gh+oPRB, gl+oPRB, Tv);

    // cval2 = probs @ v_x  (causal K-trunc)
    hg<64,true,false,false,false,true><<<dim3(1,16,16), blk>>>(
        gh+oPRB, gl+oPRB, Tv, (long)Hv*Tv*Tv, (long)Tv*Tv,
        gh+oVXT, gl+oVXT, Tv, (long)Hv*Dv*Tv, (long)Dv*Tv,
        gf+fC2, nullptr, nullptr, Cv, (long)Tv*Cv, (long)Dv, nullptr, Tv, Hv, 1.0f);

    // satt = q_x @ k_x^T * SCL  (causal tile-skip)
    hg<128,true,false,false,true,false><<<dim3(16,16,16), blk>>>(
        gh+oQKVX, gl+oQKVX, 3*Cv, (long)Tv*3*Cv, (long)Dv,
        gh+oQKVX+Cv, gl+oQKVX+Cv, 3*Cv, (long)Tv*3*Cv, (long)Dv,
        gf+fBG, nullptr, nullptr, Tv, (long)Hv*Tv*Tv, (long)Tv*Tv, nullptr, Dv, Hv, SCL);

    sm_k<true><<<dim3(Tv, BHv), blk>>>(gf+fBG, gh+oPRB, gl+oPRB, Tv);

    // sval = probs @ v_x  (f32 + pair)
    hg<64,true,true,false,false,true><<<dim3(1,16,16), blk>>>(
        gh+oPRB, gl+oPRB, Tv, (long)Hv*Tv*Tv, (long)Tv*Tv,
        gh+oVXT, gl+oVXT, Tv, (long)Hv*Dv*Tv, (long)Dv*Tv,
        gf+fSV, gh+oSV, gl+oSV, Cv, (long)Tv*Cv, (long)Dv, nullptr, Tv, Hv, 1.0f);

    // cval = cval1 + cval2 (f32 + pair)
    add_k<<<(unsigned)((nTC + 255) / 256), blk>>>(gf+fC1, gf+fC2, gf+fCV, gh+oCV, gl+oCV, nTC);

    // gates
    hg<128,true,false,true,false,false><<<dim3(4,32,1), blk>>>(
        gh+oSV, gl+oSV, Cv, 0,0, gh+oWGS, gl+oWGS, Cv, 0,0,
        gf+fT1, nullptr, nullptr, Cv, 0,0, bgs, Cv, 1, 1.0f);
    hg<128,true,false,true,false,false><<<dim3(4,32,1), blk>>>(
        gh+oCV, gl+oCV, Cv, 0,0, gh+oWGC, gl+oWGC, Cv, 0,0,
        gf+fT2, nullptr, nullptr, Cv, 0,0, bgc, Cv, 1, 1.0f);

    gate_k<<<(unsigned)((nTC + 255) / 256), blk>>>(gf+fT1, gf+fT2, gf+fCV, gf+fSV, gh+oT3, gl+oT3, nTC);

    // out = t3 @ Wp + bp
    hg<128,true,false,true,false,false><<<dim3(4,32,1), blk>>>(
        gh+oT3, gl+oT3, Cv, 0,0, gh+oWP, gl+oWP, Cv, 0,0,
        out, nullptr, nullptr, Cv, 0,0, bp, Cv, 1, 1.0f);
}

// round 8
// speedup vs baseline: 8.3218x; 1.6031x over previous
#include <cuda_runtime.h>
#include <cuda_bf16.h>
#include <cstdint>
#include <math.h>

#define BBv 2
#define Tv 2048
#define Mv 512
#define Cv 512
#define Hv 8
#define Dv 64
#define BHv 16
#define SCL 0.125f
typedef __nv_bfloat16 bf;

// ---------- bf16 pair pool offsets (elements) ----------
constexpr long oXB   = 0;
constexpr long oYB   = oXB   + (long)BBv*Tv*Cv;
constexpr long oWQX  = oYB   + (long)BBv*Mv*Cv;
constexpr long oWQY  = oWQX  + (long)Cv*3*Cv;
constexpr long oWGS  = oWQY  + (long)Cv*3*Cv;
constexpr long oWGC  = oWGS  + (long)Cv*Cv;
constexpr long oWP   = oWGC  + (long)Cv*Cv;
constexpr long oQKVX = oWP   + (long)Cv*Cv;
constexpr long oQKVY = oQKVX + (long)BBv*Tv*3*Cv;
constexpr long oQXG  = oQKVY + (long)BBv*Mv*3*Cv;
constexpr long oGT   = oQXG  + (long)BHv*Tv*Dv;
constexpr long oVXT  = oGT   + (long)BHv*Dv*Dv;
constexpr long oVYT  = oVXT  + (long)BHv*Dv*Tv;
constexpr long oSV   = oVYT  + (long)BHv*Dv*Mv;
constexpr long oCV   = oSV   + (long)BBv*Tv*Cv;
constexpr long oT3   = oCV   + (long)BBv*Tv*Cv;
constexpr long NBF   = oT3   + (long)BBv*Tv*Cv;
// ---------- fp32 pool ----------
constexpr long fC1 = 0;
constexpr long fC2 = fC1 + (long)BBv*Tv*Cv;
constexpr long fCV = fC2 + (long)BBv*Tv*Cv;
constexpr long fSV = fCV + (long)BBv*Tv*Cv;
constexpr long fT1 = fSV + (long)BBv*Tv*Cv;
constexpr long fT2 = fT1 + (long)BBv*Tv*Cv;
constexpr long NF_ = fT2 + (long)BBv*Tv*Cv;

__device__ bf    g_h[NBF];
__device__ bf    g_l[NBF];
__device__ float g_f[NF_];

// ---------- warp MMA helpers ----------
__device__ __forceinline__ uint32_t smem_u32(const void* p) {
    uint32_t a;
    asm("{ .reg .u64 t; cvta.to.shared.u64 t, %1; cvt.u32.u64 %0, t; }" : "=r"(a) : "l"(p));
    return a;
}
#define LDM4(r, addr) asm volatile( \
    "ldmatrix.sync.aligned.m8n8.x4.shared.b16 {%0,%1,%2,%3}, [%4];" \
    : "=r"((r)[0]), "=r"((r)[1]), "=r"((r)[2]), "=r"((r)[3]) : "r"(addr))
#define MMA(c, a, b) asm volatile( \
    "mma.sync.aligned.m16n8k16.row.col.f32.bf16.bf16.f32 " \
    "{%0,%1,%2,%3}, {%4,%5,%6,%7}, {%8,%9}, {%0,%1,%2,%3};" \
    : "+f"((c)[0]), "+f"((c)[1]), "+f"((c)[2]), "+f"((c)[3]) \
    : "r"((a)[0]), "r"((a)[1]), "r"((a)[2]), "r"((a)[3]), "r"((b)[0]), "r"((b)[1]))

__device__ __forceinline__ uint32_t packbf(float a, float b) {
    __nv_bfloat162 t; t.x = __float2bfloat16(a); t.y = __float2bfloat16(b);
    return *reinterpret_cast<uint32_t*>(&t);
}

// ---------- HMMA split-bf16 GEMM: C = alpha*(A@B^T) (+bias) -------------------
template<int TN, bool F32O, bool PO, bool BIAS>
__global__ void __launch_bounds__(256) hg(
    const bf* __restrict__ Ah, const bf* __restrict__ Al, int lda, long sAb, long sAh_,
    const bf* __restrict__ Bh, const bf* __restrict__ Bl, int ldb, long sBb, long sBh_,
    float* __restrict__ C, bf* __restrict__ Ch, bf* __restrict__ Cl, int ldc, long sCb, long sCh_,
    const float* __restrict__ bias, int K, int Hn, float alpha)
{
    constexpr int NFRAG = TN / 16;
    int m0 = blockIdx.y * 128, n0 = blockIdx.x * TN;
    int z = blockIdx.z, bb = z / Hn, hh = z - bb * Hn;
    const bf* pAh = Ah + bb * sAb + hh * sAh_;
    const bf* pAl = Al + bb * sAb + hh * sAh_;
    const bf* pBh = Bh + bb * sBb + hh * sBh_;
    const bf* pBl = Bl + bb * sBb + hh * sBh_;
    long co = bb * sCb + hh * sCh_;

    __shared__ bf sA[2][128][40];
    __shared__ bf sB[2][TN][40];
    uint32_t baseA = smem_u32(&sA[0][0][0]);
    uint32_t baseB = smem_u32(&sB[0][0][0]);

    int tid = threadIdx.x, lane = tid & 31, wid = tid >> 5;
    int wm = (wid & 3) * 32, wn = (wid >> 2) * (TN / 2);

    float acc[2][NFRAG][4];
    #pragma unroll
    for (int i = 0; i < 2; ++i)
        #pragma unroll
        for (int j = 0; j < NFRAG; ++j)
            #pragma unroll
            for (int q = 0; q < 4; ++q) acc[i][j][q] = 0.f;

    int kst = K >> 5;
    int aRow = (lane & 15), aK = (lane >> 4) * 8;
    int bRow = (lane & 7) + ((lane >> 4) & 1) * 8, bK = ((lane >> 3) & 1) * 8;

    for (int s = 0; s < kst; ++s) {
        int k0 = s << 5;
        #pragma unroll
        for (int i = 0; i < 2; ++i) {
            int q = tid + i * 256, r = q >> 2, sg = (q & 3) * 8;
            long go = (long)(m0 + r) * lda + k0 + sg;
            *(uint4*)&sA[0][r][sg] = *(const uint4*)(pAh + go);
            *(uint4*)&sA[1][r][sg] = *(const uint4*)(pAl + go);
        }
        #pragma unroll
        for (int i = 0; i < TN / 64; ++i) {
            int q = tid + i * 256, r = q >> 2, sg = (q & 3) * 8;
            long go = (long)(n0 + r) * ldb + k0 + sg;
            *(uint4*)&sB[0][r][sg] = *(const uint4*)(pBh + go);
            *(uint4*)&sB[1][r][sg] = *(const uint4*)(pBl + go);
        }
        __syncthreads();

        #pragma unroll
        for (int kk = 0; kk < 2; ++kk) {
            uint32_t ah[2][4], al[2][4];
            #pragma unroll
            for (int mf = 0; mf < 2; ++mf) {
                uint32_t off = (uint32_t)((wm + mf * 16 + aRow) * 40 + kk * 16 + aK) * 2;
                LDM4(ah[mf], baseA + off);
                LDM4(al[mf], baseA + 128 * 40 * 2 + off);
            }
            uint32_t bh[NFRAG][2], bl[NFRAG][2];
            #pragma unroll
            for (int np = 0; np < NFRAG / 2; ++np) {
                uint32_t off = (uint32_t)((wn + np * 16 + bRow) * 40 + kk * 16 + bK) * 2;
                uint32_t t[4];
                LDM4(t, baseB + off);
                bh[np*2][0] = t[0]; bh[np*2][1] = t[1]; bh[np*2+1][0] = t[2]; bh[np*2+1][1] = t[3];
                LDM4(t, baseB + TN * 40 * 2 + off);
                bl[np*2][0] = t[0]; bl[np*2][1] = t[1]; bl[np*2+1][0] = t[2]; bl[np*2+1][1] = t[3];
            }
            #pragma unroll
            for (int mf = 0; mf < 2; ++mf)
                #pragma unroll
                for (int nf = 0; nf < NFRAG; ++nf) {
                    MMA(acc[mf][nf], ah[mf], bh[nf]);
                    MMA(acc[mf][nf], ah[mf], bl[nf]);
                    MMA(acc[mf][nf], al[mf], bh[nf]);
                }
        }
        __syncthreads();
    }

    int rb = m0 + wm + (lane >> 2);
    int cb = n0 + wn + (lane & 3) * 2;
    #pragma unroll
    for (int mf = 0; mf < 2; ++mf)
        #pragma unroll
        for (int half = 0; half < 2; ++half) {
            long row = rb + mf * 16 + half * 8;
            #pragma unroll
            for (int nf = 0; nf < NFRAG; ++nf) {
                int cc = cb + nf * 8;
                float v0 = alpha * acc[mf][nf][half * 2 + 0];
                float v1 = alpha * acc[mf][nf][half * 2 + 1];
                if (BIAS) { v0 += bias[cc]; v1 += bias[cc + 1]; }
                long base = co + row * (long)ldc + cc;
                if (F32O) { C[base] = v0; C[base + 1] = v1; }
                if (PO) {
                    bf h0 = __float2bfloat16(v0), h1 = __float2bfloat16(v1);
                    __nv_bfloat162 hp; hp.x = h0; hp.y = h1;
                    __nv_bfloat162 lp;
                    lp.x = __float2bfloat16(v0 - __bfloat162float(h0));
                    lp.y = __float2bfloat16(v1 - __bfloat162float(h1));
                    *reinterpret_cast<__nv_bfloat162*>(Ch + base) = hp;
                    *reinterpret_cast<__nv_bfloat162*>(Cl + base) = lp;
                }
            }
        }
}

// ---------- fused flash attention: out = softmax(A@K^T * scale) @ V -----------
// A,K: [rows, 64] K-major hi/lo.  V: [BH][64][S] (d-major, i.e. V^T) hi/lo.
// Block: 128 q-rows, 8 warps x 16 rows. Col tiles of 64.
template<bool CAUSAL, bool PAIRO>
__global__ void __launch_bounds__(256) fa_k(
    const bf* __restrict__ Ah, const bf* __restrict__ Al, int lda, long sAb, long sAh_,
    const bf* __restrict__ Kh, const bf* __restrict__ Kl, int ldk, long sKb, long sKh_,
    const bf* __restrict__ Vh, const bf* __restrict__ Vl, int S_,
    float* __restrict__ O, bf* __restrict__ Oh, bf* __restrict__ Ol,
    int ldo, long sOb, long sOh_, float scale)
{
    int z = blockIdx.y, bb = z >> 3, hh = z & 7;
    int m0 = (int)(gridDim.x - 1 - blockIdx.x) * 128;   // heavy blocks first
    const bf* pAh = Ah + bb * sAb + hh * sAh_;
    const bf* pAl = Al + bb * sAb + hh * sAh_;
    const bf* pKh = Kh + bb * sKb + hh * sKh_;
    const bf* pKl = Kl + bb * sKb + hh * sKh_;
    const bf* pVh = Vh + (long)z * 64 * S_;
    const bf* pVl = Vl + (long)z * 64 * S_;
    long co = (long)bb * sOb + (long)hh * sOh_;

    // smem (bf16 elems): K_hi@0, K_lo@4608, V_hi@9216, V_lo@13824 (each 64x72)
    // q staging reuses: q_hi@0 (128x72 = 9216), q_lo@9216
    __shared__ __align__(16) bf smv[18432];
    uint32_t sbase = smem_u32(smv);
    int tid = threadIdx.x, lane = tid & 31, wid = tid >> 5;
    int wrow = wid * 16;

    // stage q block [128x64] hi/lo
    #pragma unroll
    for (int i = 0; i < 4; ++i) {
        int q = tid + i * 256, r = q >> 3, ch = q & 7;
        long go = (long)(m0 + r) * lda + ch * 8;
        *(uint4*)&smv[r * 72 + ch * 8]        = *(const uint4*)(pAh + go);
        *(uint4*)&smv[9216 + r * 72 + ch * 8] = *(const uint4*)(pAl + go);
    }
    __syncthreads();

    int aRow = lane & 15, aK = (lane >> 4) * 8;
    int bRow = (lane & 7) + ((lane >> 4) & 1) * 8, bK = ((lane >> 3) & 1) * 8;
    uint32_t qh[4][4], ql[4][4];
    #pragma unroll
    for (int kk = 0; kk < 4; ++kk) {
        uint32_t off = (uint32_t)((wrow + aRow) * 72 + kk * 16 + aK) * 2;
        LDM4(qh[kk], sbase + off);
        LDM4(ql[kk], sbase + 9216 * 2 + off);
    }
    __syncthreads();

    float o[8][4];
    #pragma unroll
    for (int i = 0; i < 8; ++i)
        #pragma unroll
        for (int q = 0; q < 4; ++q) o[i][q] = 0.f;
    float mr0 = -INFINITY, mr1 = -INFINITY, l0 = 0.f, l1 = 0.f;

    int nt = CAUSAL ? ((m0 >> 6) + 2) : (S_ >> 6);
    int row0 = m0 + wrow + (lane >> 2);

    for (int ct = 0; ct < nt; ++ct) {
        int c0 = ct << 6;
        #pragma unroll
        for (int i = 0; i < 2; ++i) {
            int q = tid + i * 256, r = q >> 3, ch = q & 7;
            long gk = (long)(c0 + r) * ldk + ch * 8;
            *(uint4*)&smv[r * 72 + ch * 8]         = *(const uint4*)(pKh + gk);
            *(uint4*)&smv[4608 + r * 72 + ch * 8]  = *(const uint4*)(pKl + gk);
            long gv = (long)r * S_ + c0 + ch * 8;
            *(uint4*)&smv[9216 + r * 72 + ch * 8]  = *(const uint4*)(pVh + gv);
            *(uint4*)&smv[13824 + r * 72 + ch * 8] = *(const uint4*)(pVl + gv);
        }
        __syncthreads();

        // scores: 16x64 per warp
        float s[8][4];
        #pragma unroll
        for (int i = 0; i < 8; ++i)
            #pragma unroll
            for (int q = 0; q < 4; ++q) s[i][q] = 0.f;

        #pragma unroll
        for (int kk = 0; kk < 4; ++kk) {
            uint32_t kh[8][2], kl[8][2];
            #pragma unroll
            for (int np = 0; np < 4; ++np) {
                uint32_t off = (uint32_t)((np * 16 + bRow) * 72 + kk * 16 + bK) * 2;
                uint32_t t[4];
                LDM4(t, sbase + off);
                kh[np*2][0] = t[0]; kh[np*2][1] = t[1]; kh[np*2+1][0] = t[2]; kh[np*2+1][1] = t[3];
                LDM4(t, sbase + 4608 * 2 + off);
                kl[np*2][0] = t[0]; kl[np*2][1] = t[1]; kl[np*2+1][0] = t[2]; kl[np*2+1][1] = t[3];
            }
            #pragma unroll
            for (int nf = 0; nf < 8; ++nf) {
                MMA(s[nf], qh[kk], kh[nf]);
                MMA(s[nf], qh[kk], kl[nf]);
                MMA(s[nf], ql[kk], kh[nf]);
            }
        }
        #pragma unroll
        for (int nf = 0; nf < 8; ++nf) {
            #pragma unroll
            for (int q = 0; q < 4; ++q) s[nf][q] *= scale;
        }
        if (CAUSAL && (c0 + 63 > m0 + wrow)) {
            #pragma unroll
            for (int nf = 0; nf < 8; ++nf) {
                int col = c0 + nf * 8 + (lane & 3) * 2;
                if (col     > row0)     s[nf][0] = -1e30f;
                if (col + 1 > row0)     s[nf][1] = -1e30f;
                if (col     > row0 + 8) s[nf][2] = -1e30f;
                if (col + 1 > row0 + 8) s[nf][3] = -1e30f;
            }
        }
        // row max (rows r: regs 0,1 ; rows r+8: regs 2,3), reduce over 4 lanes
        float t0 = -INFINITY, t1 = -INFINITY;
        #pragma unroll
        for (int nf = 0; nf < 8; ++nf) {
            t0 = fmaxf(t0, fmaxf(s[nf][0], s[nf][1]));
            t1 = fmaxf(t1, fmaxf(s[nf][2], s[nf][3]));
        }
        t0 = fmaxf(t0, __shfl_xor_sync(0xffffffffu, t0, 1));
        t0 = fmaxf(t0, __shfl_xor_sync(0xffffffffu, t0, 2));
        t1 = fmaxf(t1, __shfl_xor_sync(0xffffffffu, t1, 1));
        t1 = fmaxf(t1, __shfl_xor_sync(0xffffffffu, t1, 2));
        float mn0 = fmaxf(mr0, t0), mn1 = fmaxf(mr1, t1);
        float cr0 = __expf(mr0 - mn0), cr1 = __expf(mr1 - mn1);
        float sum0 = 0.f, sum1 = 0.f;
        #pragma unroll
        for (int nf = 0; nf < 8; ++nf) {
            s[nf][0] = __expf(s[nf][0] - mn0);
            s[nf][1] = __expf(s[nf][1] - mn0);
            s[nf][2] = __expf(s[nf][2] - mn1);
            s[nf][3] = __expf(s[nf][3] - mn1);
            sum0 += s[nf][0] + s[nf][1];
            sum1 += s[nf][2] + s[nf][3];
        }
        sum0 += __shfl_xor_sync(0xffffffffu, sum0, 1);
        sum0 += __shfl_xor_sync(0xffffffffu, sum0, 2);
        sum1 += __shfl_xor_sync(0xffffffffu, sum1, 1);
        sum1 += __shfl_xor_sync(0xffffffffu, sum1, 2);
        l0 = l0 * cr0 + sum0; l1 = l1 * cr1 + sum1;
        mr0 = mn0; mr1 = mn1;
        #pragma unroll
        for (int nf = 0; nf < 8; ++nf) {
            o[nf][0] *= cr0; o[nf][1] *= cr0; o[nf][2] *= cr1; o[nf][3] *= cr1;
        }
        // PV: P (16 x 64, bf16 pair) @ V (64 x 64)
        #pragma unroll
        for (int kk2 = 0; kk2 < 4; ++kk2) {
            uint32_t Ph[4], Pl[4];
            {
                float a0 = s[2*kk2][0],   a1 = s[2*kk2][1];
                float a2 = s[2*kk2][2],   a3 = s[2*kk2][3];
                float a4 = s[2*kk2+1][0], a5 = s[2*kk2+1][1];
                float a6 = s[2*kk2+1][2], a7 = s[2*kk2+1][3];
                bf h0 = __float2bfloat16(a0), h1 = __float2bfloat16(a1);
                bf h2 = __float2bfloat16(a2), h3 = __float2bfloat16(a3);
                bf h4 = __float2bfloat16(a4), h5 = __float2bfloat16(a5);
                bf h6 = __float2bfloat16(a6), h7 = __float2bfloat16(a7);
                Ph[0] = packbf(__bfloat162float(h0), __bfloat162float(h1));
                Ph[1] = packbf(__bfloat162float(h2), __bfloat162float(h3));
                Ph[2] = packbf(__bfloat162float(h4), __bfloat162float(h5));
                Ph[3] = packbf(__bfloat162float(h6), __bfloat162float(h7));
                Pl[0] = packbf(a0 - __bfloat162float(h0), a1 - __bfloat162float(h1));
                Pl[1] = packbf(a2 - __bfloat162float(h2), a3 - __bfloat162float(h3));
                Pl[2] = packbf(a4 - __bfloat162float(h4), a5 - __bfloat162float(h5));
                Pl[3] = packbf(a6 - __bfloat162float(h6), a7 - __bfloat162float(h7));
            }
            uint32_t vh[8][2], vl[8][2];
            #pragma unroll
            for (int np = 0; np < 4; ++np) {
                uint32_t off = (uint32_t)((np * 16 + bRow) * 72 + kk2 * 16 + bK) * 2;
                uint32_t t[4];
                LDM4(t, sbase + 9216 * 2 + off);
                vh[np*2][0] = t[0]; vh[np*2][1] = t[1]; vh[np*2+1][0] = t[2]; vh[np*2+1][1] = t[3];
                LDM4(t, sbase + 13824 * 2 + off);
                vl[np*2][0] = t[0]; vl[np*2][1] = t[1]; vl[np*2+1][0] = t[2]; vl[np*2+1][1] = t[3];
            }
            #pragma unroll
            for (int nf = 0; nf < 8; ++nf) {
                MMA(o[nf], Ph, vh[nf]);
                MMA(o[nf], Ph, vl[nf]);
                MMA(o[nf], Pl, vh[nf]);
            }
        }
        __syncthreads();
    }

    float inv0 = 1.f / l0, inv1 = 1.f / l1;
    #pragma unroll
    for (int nf = 0; nf < 8; ++nf) {
        int col = nf * 8 + (lane & 3) * 2;
        float v0 = o[nf][0] * inv0, v1 = o[nf][1] * inv0;
        float v2 = o[nf][2] * inv1, v3 = o[nf][3] * inv1;
        long b0 = co + (long)row0 * ldo + col;
        long b1 = co + (long)(row0 + 8) * ldo + col;
        O[b0] = v0; O[b0 + 1] = v1; O[b1] = v2; O[b1 + 1] = v3;
        if (PAIRO) {
            bf h0 = __float2bfloat16(v0), h1 = __float2bfloat16(v1);
            bf h2 = __float2bfloat16(v2), h3 = __float2bfloat16(v3);
            __nv_bfloat162 hp0; hp0.x = h0; hp0.y = h1;
            __nv_bfloat162 hp1; hp1.x = h2; hp1.y = h3;
            __nv_bfloat162 lp0, lp1;
            lp0.x = __float2bfloat16(v0 - __bfloat162float(h0));
            lp0.y = __float2bfloat16(v1 - __bfloat162float(h1));
            lp1.x = __float2bfloat16(v2 - __bfloat162float(h2));
            lp1.y = __float2bfloat16(v3 - __bfloat162float(h3));
            *reinterpret_cast<__nv_bfloat162*>(Oh + b0) = hp0;
            *reinterpret_cast<__nv_bfloat162*>(Ol + b0) = lp0;
            *reinterpret_cast<__nv_bfloat162*>(Oh + b1) = hp1;
            *reinterpret_cast<__nv_bfloat162*>(Ol + b1) = lp1;
        }
    }
}

// ---------- G^T = SCL^2 * (k_y^T q_y)^T per head : [BH,64,64] bf16 pair -------
__global__ void __launch_bounds__(256) g_k(const bf* __restrict__ qh, const bf* __restrict__ ql,
                                           bf* __restrict__ goh, bf* __restrict__ gol)
{
    int z = blockIdx.x, b = z >> 3, h = z & 7;
    long kyo = (long)b * Mv * 3 * Cv + (long)h * Dv + Cv;
    long qyo = (long)b * Mv * 3 * Cv + (long)h * Dv;
    __shared__ float sky[64][65], sqy[64][65];
    int tid = threadIdx.x;
    int d2 = tid & 63, gg = tid >> 6;
    float acc[16];
    #pragma unroll
    for (int i = 0; i < 16; ++i) acc[i] = 0.f;
    for (int m0 = 0; m0 < Mv; m0 += 64) {
        #pragma unroll
        for (int i = 0; i < 16; ++i) {
            int q = tid + i * 256;
            int mm = q >> 6, dd = q & 63;
            long ik = kyo + (long)(m0 + mm) * 3 * Cv + dd;
            long iq = qyo + (long)(m0 + mm) * 3 * Cv + dd;
            sky[mm][dd] = __bfloat162float(qh[ik]) + __bfloat162float(ql[ik]);
            sqy[mm][dd] = __bfloat162float(qh[iq]) + __bfloat162float(ql[iq]);
        }
        __syncthreads();
        for (int mm = 0; mm < 64; ++mm) {
            float qv = sqy[mm][d2];
            #pragma unroll
            for (int i = 0; i < 16; ++i)
                acc[i] += sky[mm][gg * 16 + i] * qv;
        }
        __syncthreads();
    }
    long base = (long)z * 4096 + (long)d2 * 64 + gg * 16;
    #pragma unroll
    for (int i = 0; i < 16; ++i) {
        float v = acc[i] * (SCL * SCL);
        bf hh = __float2bfloat16(v);
        goh[base + i] = hh;
        gol[base + i] = __float2bfloat16(v - __bfloat162float(hh));
    }
}

// ---------- small utility kernels ----------
__global__ void split_k(const float* __restrict__ in, bf* __restrict__ oh, bf* __restrict__ ol, long n) {
    long i = (long)blockIdx.x * 256 + threadIdx.x;
    if (i < n) {
        float v = in[i]; bf h = __float2bfloat16(v);
        oh[i] = h; ol[i] = __float2bfloat16(v - __bfloat162float(h));
    }
}
__global__ void splitT_k(const float* __restrict__ in, bf* __restrict__ oh, bf* __restrict__ ol, int Kd, int Nd) {
    long i = (long)blockIdx.x * 256 + threadIdx.x;
    if (i < (long)Kd * Nd) {
        int n = (int)(i / Kd), k = (int)(i % Kd);
        float v = in[(long)k * Nd + n]; bf h = __float2bfloat16(v);
        oh[i] = h; ol[i] = __float2bfloat16(v - __bfloat162float(h));
    }
}
__global__ void vT_k(const bf* __restrict__ ih, const bf* __restrict__ il,
                     bf* __restrict__ oh, bf* __restrict__ ol, int L) {
    int z = blockIdx.y, b = z / Hv, h = z % Hv;
    long iof = (long)b * L * 3 * Cv + (long)h * Dv + 2 * Cv;
    long oof = (long)z * Dv * L;
    int idx = blockIdx.x * 256 + threadIdx.x;
    int d = idx / L, l = idx % L;
    long ii = iof + (long)l * 3 * Cv + d;
    oh[oof + idx] = ih[ii]; ol[oof + idx] = il[ii];
}
__global__ void add_k(const float* __restrict__ a, const float* __restrict__ b,
                      float* __restrict__ of, bf* __restrict__ oh, bf* __restrict__ ol, long n) {
    long i = (long)blockIdx.x * 256 + threadIdx.x;
    if (i < n) {
        float v = a[i] + b[i]; of[i] = v;
        bf h = __float2bfloat16(v);
        oh[i] = h; ol[i] = __float2bfloat16(v - __bfloat162float(h));
    }
}
__global__ void gate_k(const float* __restrict__ t1, const float* __restrict__ t2,
                       const float* __restrict__ cv, const float* __restrict__ sv,
                       bf* __restrict__ oh, bf* __restrict__ ol, long n) {
    long i = (long)blockIdx.x * 256 + threadIdx.x;
    if (i < n) {
        float g1 = 1.f / (1.f + __expf(-t1[i]));
        float g2 = 1.f / (1.f + __expf(-t2[i]));
        float v = g1 * cv[i] + g2 * sv[i];
        bf h = __float2bfloat16(v);
        oh[i] = h; ol[i] = __float2bfloat16(v - __bfloat162float(h));
    }
}

// ------------------------------------------------------------------------------
extern "C" void kernel_launch(void* const* d_in, const int* in_sizes, int n_in,
                              void* d_out, int out_size)
{
    const float* x      = (const float*)d_in[0];
    const float* y      = (const float*)d_in[1];
    const float* Wqkv_x = (const float*)d_in[3];
    const float* bqkv_x = (const float*)d_in[4];
    const float* Wqkv_y = (const float*)d_in[5];
    const float* bqkv_y = (const float*)d_in[6];
    const float* Wgs    = (const float*)d_in[7];
    const float* bgs    = (const float*)d_in[8];
    const float* Wgc    = (const float*)d_in[9];
    const float* bgc    = (const float*)d_in[10];
    const float* Wp     = (const float*)d_in[11];
    const float* bp     = (const float*)d_in[12];
    float* out = (float*)d_out;

    bf *gh, *gl; float* gf;
    cudaGetSymbolAddress((void**)&gh, g_h);
    cudaGetSymbolAddress((void**)&gl, g_l);
    cudaGetSymbolAddress((void**)&gf, g_f);

    dim3 blk(256);
    long nTC = (long)BBv * Tv * Cv;

    // input / weight splits
    split_k<<<(unsigned)((nTC + 255) / 256), blk>>>(x, gh + oXB, gl + oXB, nTC);
    split_k<<<(unsigned)((BBv*Mv*Cv + 255) / 256), blk>>>(y, gh + oYB, gl + oYB, (long)BBv*Mv*Cv);
    splitT_k<<<(unsigned)((Cv*3*Cv + 255) / 256), blk>>>(Wqkv_x, gh + oWQX, gl + oWQX, Cv, 3*Cv);
    splitT_k<<<(unsigned)((Cv*3*Cv + 255) / 256), blk>>>(Wqkv_y, gh + oWQY, gl + oWQY, Cv, 3*Cv);
    splitT_k<<<(unsigned)((Cv*Cv + 255) / 256), blk>>>(Wgs, gh + oWGS, gl + oWGS, Cv, Cv);
    splitT_k<<<(unsigned)((Cv*Cv + 255) / 256), blk>>>(Wgc, gh + oWGC, gl + oWGC, Cv, Cv);
    splitT_k<<<(unsigned)((Cv*Cv + 255) / 256), blk>>>(Wp,  gh + oWP,  gl + oWP,  Cv, Cv);

    // qkv projections (pair out)
    hg<128,false,true,true><<<dim3(12,32,1), blk>>>(
        gh+oXB, gl+oXB, Cv, 0,0, gh+oWQX, gl+oWQX, Cv, 0,0,
        nullptr, gh+oQKVX, gl+oQKVX, 3*Cv, 0,0, bqkv_x, Cv, 1, 1.0f);
    hg<128,false,true,true><<<dim3(12,8,1), blk>>>(
        gh+oYB, gl+oYB, Cv, 0,0, gh+oWQY, gl+oWQY, Cv, 0,0,
        nullptr, gh+oQKVY, gl+oQKVY, 3*Cv, 0,0, bqkv_y, Cv, 1, 1.0f);

    // v transposes -> [BH][64][L]
    vT_k<<<dim3(Dv*Tv/256, BHv), blk>>>(gh+oQKVX, gl+oQKVX, gh+oVXT, gl+oVXT, Tv);
    vT_k<<<dim3(Dv*Mv/256, BHv), blk>>>(gh+oQKVY, gl+oQKVY, gh+oVYT, gl+oVYT, Mv);

    // G^T = SCL^2 * (k_y^T @ q_y)^T  [BH,64,64]
    g_k<<<BHv, blk>>>(gh+oQKVY, gl+oQKVY, gh+oGT, gl+oGT);

    // qxG = q_x @ G  [BH,T,64]  (pair out)
    hg<64,false,true,false><<<dim3(1,16,16), blk>>>(
        gh+oQKVX, gl+oQKVX, 3*Cv, (long)Tv*3*Cv, (long)Dv,
        gh+oGT, gl+oGT, 64, (long)Hv*Dv*Dv, (long)Dv*Dv,
        nullptr, gh+oQXG, gl+oQXG, Dv, (long)Hv*Tv*Dv, (long)Tv*Dv, nullptr, Dv, Hv, 1.0f);

    // cval1 = softmax(q_x k_y^T) v_y  (fused, non-causal, S=512)
    fa_k<false,false><<<dim3(16,16), blk>>>(
        gh+oQKVX, gl+oQKVX, 3*Cv, (long)Tv*3*Cv, (long)Dv,
        gh+oQKVY+Cv, gl+oQKVY+Cv, 3*Cv, (long)Mv*3*Cv, (long)Dv,
        gh+oVYT, gl+oVYT, Mv,
        gf+fC1, nullptr, nullptr, Cv, (long)Tv*Cv, (long)Dv, SCL);

    // cval2 = softmax_causal(qxG k_x^T) v_x  (fused)
    fa_k<true,false><<<dim3(16,16), blk>>>(
        gh+oQXG, gl+oQXG, Dv, (long)Hv*Tv*Dv, (long)Tv*Dv,
        gh+oQKVX+Cv, gl+oQKVX+Cv, 3*Cv, (long)Tv*3*Cv, (long)Dv,
        gh+oVXT, gl+oVXT, Tv,
        gf+fC2, nullptr, nullptr, Cv, (long)Tv*Cv, (long)Dv, SCL);

    // sval = softmax_causal(q_x k_x^T) v_x  (fused, pair out)
    fa_k<true,true><<<dim3(16,16), blk>>>(
        gh+oQKVX, gl+oQKVX, 3*Cv, (long)Tv*3*Cv, (long)Dv,
        gh+oQKVX+Cv, gl+oQKVX+Cv, 3*Cv, (long)Tv*3*Cv, (long)Dv,
        gh+oVXT, gl+oVXT, Tv,
        gf+fSV, gh+oSV, gl+oSV, Cv, (long)Tv*Cv, (long)Dv, SCL);

    // cval = cval1 + cval2 (f32 + pair)
    add_k<<<(unsigned)((nTC + 255) / 256), blk>>>(gf+fC1, gf+fC2, gf+fCV, gh+oCV, gl+oCV, nTC);

    // gates
    hg<128,true,false,true><<<dim3(4,32,1), blk>>>(
        gh+oSV, gl+oSV, Cv, 0,0, gh+oWGS, gl+oWGS, Cv, 0,0,
        gf+fT1, nullptr, nullptr, Cv, 0,0, bgs, Cv, 1, 1.0f);
    hg<128,true,false,true><<<dim3(4,32,1), blk>>>(
        gh+oCV, gl+oCV, Cv, 0,0, gh+oWGC, gl+oWGC, Cv, 0,0,
        gf+fT2, nullptr, nullptr, Cv, 0,0, bgc, Cv, 1, 1.0f);

    gate_k<<<(unsigned)((nTC + 255) / 256), blk>>>(gf+fT1, gf+fT2, gf+fCV, gf+fSV, gh+oT3, gl+oT3, nTC);

    // out = t3 @ Wp + bp
    hg<128,true,false,true><<<dim3(4,32,1), blk>>>(
        gh+oT3, gl+oT3, Cv, 0,0, gh+oWP, gl+oWP, Cv, 0,0,
        out, nullptr, nullptr, Cv, 0,0, bp, Cv, 1, 1.0f);
}

// round 9
// speedup vs baseline: 8.8058x; 1.0582x over previous
#include <cuda_runtime.h>
#include <cuda_bf16.h>
#include <cstdint>
#include <math.h>

#define BBv 2
#define Tv 2048
#define Mv 512
#define Cv 512
#define Hv 8
#define Dv 64
#define BHv 16
#define SCL 0.125f
typedef __nv_bfloat16 bf;

// ---------- bf16 pair pool offsets (elements) ----------
constexpr long oXB   = 0;
constexpr long oYB   = oXB   + (long)BBv*Tv*Cv;
constexpr long oWQX  = oYB   + (long)BBv*Mv*Cv;
constexpr long oWQY  = oWQX  + (long)Cv*3*Cv;
constexpr long oWGS  = oWQY  + (long)Cv*3*Cv;
constexpr long oWGC  = oWGS  + (long)Cv*Cv;
constexpr long oWP   = oWGC  + (long)Cv*Cv;
constexpr long oQKVX = oWP   + (long)Cv*Cv;
constexpr long oQKVY = oQKVX + (long)BBv*Tv*3*Cv;
constexpr long oQXG  = oQKVY + (long)BBv*Mv*3*Cv;
constexpr long oGT   = oQXG  + (long)BHv*Tv*Dv;
constexpr long oVXT  = oGT   + (long)BHv*Dv*Dv;
constexpr long oVYT  = oVXT  + (long)BHv*Dv*Tv;
constexpr long oSV   = oVYT  + (long)BHv*Dv*Mv;
constexpr long oCV   = oSV   + (long)BBv*Tv*Cv;
constexpr long oT3   = oCV   + (long)BBv*Tv*Cv;
constexpr long NBF   = oT3   + (long)BBv*Tv*Cv;
// ---------- fp32 pool ----------
constexpr long fC1 = 0;
constexpr long fSV = fC1 + (long)BBv*Tv*Cv;
constexpr long fT1 = fSV + (long)BBv*Tv*Cv;
constexpr long fT2 = fT1 + (long)BBv*Tv*Cv;
constexpr long NF_ = fT2 + (long)BBv*Tv*Cv;

__device__ bf    g_h[NBF];
__device__ bf    g_l[NBF];
__device__ float g_f[NF_];

// ---------- warp MMA helpers ----------
__device__ __forceinline__ uint32_t smem_u32(const void* p) {
    uint32_t a;
    asm("{ .reg .u64 t; cvta.to.shared.u64 t, %1; cvt.u32.u64 %0, t; }" : "=r"(a) : "l"(p));
    return a;
}
#define LDM4(r, addr) asm volatile( \
    "ldmatrix.sync.aligned.m8n8.x4.shared.b16 {%0,%1,%2,%3}, [%4];" \
    : "=r"((r)[0]), "=r"((r)[1]), "=r"((r)[2]), "=r"((r)[3]) : "r"(addr))
#define MMA(c, a, b) asm volatile( \
    "mma.sync.aligned.m16n8k16.row.col.f32.bf16.bf16.f32 " \
    "{%0,%1,%2,%3}, {%4,%5,%6,%7}, {%8,%9}, {%0,%1,%2,%3};" \
    : "+f"((c)[0]), "+f"((c)[1]), "+f"((c)[2]), "+f"((c)[3]) \
    : "r"((a)[0]), "r"((a)[1]), "r"((a)[2]), "r"((a)[3]), "r"((b)[0]), "r"((b)[1]))
#define CPA(sa, ga) asm volatile("cp.async.cg.shared.global [%0], [%1], 16;" :: "r"(sa), "l"(ga))
#define CPA_COMMIT() asm volatile("cp.async.commit_group;")

__device__ __forceinline__ uint32_t packbf(float a, float b) {
    __nv_bfloat162 t; t.x = __float2bfloat16(a); t.y = __float2bfloat16(b);
    return *reinterpret_cast<uint32_t*>(&t);
}

// ---------- HMMA split-bf16 GEMM: C = alpha*(A@B^T) (+bias) -------------------
template<int TN, bool F32O, bool PO, bool BIAS>
__global__ void __launch_bounds__(256) hg(
    const bf* __restrict__ Ah, const bf* __restrict__ Al, int lda, long sAb, long sAh_,
    const bf* __restrict__ Bh, const bf* __restrict__ Bl, int ldb, long sBb, long sBh_,
    float* __restrict__ C, bf* __restrict__ Ch, bf* __restrict__ Cl, int ldc, long sCb, long sCh_,
    const float* __restrict__ bias, int K, int Hn, float alpha)
{
    constexpr int NFRAG = TN / 16;
    int m0 = blockIdx.y * 128, n0 = blockIdx.x * TN;
    int z = blockIdx.z, bb = z / Hn, hh = z - bb * Hn;
    const bf* pAh = Ah + bb * sAb + hh * sAh_;
    const bf* pAl = Al + bb * sAb + hh * sAh_;
    const bf* pBh = Bh + bb * sBb + hh * sBh_;
    const bf* pBl = Bl + bb * sBb + hh * sBh_;
    long co = bb * sCb + hh * sCh_;

    __shared__ bf sA[2][128][40];
    __shared__ bf sB[2][TN][40];
    uint32_t baseA = smem_u32(&sA[0][0][0]);
    uint32_t baseB = smem_u32(&sB[0][0][0]);

    int tid = threadIdx.x, lane = tid & 31, wid = tid >> 5;
    int wm = (wid & 3) * 32, wn = (wid >> 2) * (TN / 2);

    float acc[2][NFRAG][4];
    #pragma unroll
    for (int i = 0; i < 2; ++i)
        #pragma unroll
        for (int j = 0; j < NFRAG; ++j)
            #pragma unroll
            for (int q = 0; q < 4; ++q) acc[i][j][q] = 0.f;

    int kst = K >> 5;
    int aRow = (lane & 15), aK = (lane >> 4) * 8;
    int bRow = (lane & 7) + ((lane >> 4) & 1) * 8, bK = ((lane >> 3) & 1) * 8;

    for (int s = 0; s < kst; ++s) {
        int k0 = s << 5;
        #pragma unroll
        for (int i = 0; i < 2; ++i) {
            int q = tid + i * 256, r = q >> 2, sg = (q & 3) * 8;
            long go = (long)(m0 + r) * lda + k0 + sg;
            *(uint4*)&sA[0][r][sg] = *(const uint4*)(pAh + go);
            *(uint4*)&sA[1][r][sg] = *(const uint4*)(pAl + go);
        }
        #pragma unroll
        for (int i = 0; i < TN / 64; ++i) {
            int q = tid + i * 256, r = q >> 2, sg = (q & 3) * 8;
            long go = (long)(n0 + r) * ldb + k0 + sg;
            *(uint4*)&sB[0][r][sg] = *(const uint4*)(pBh + go);
            *(uint4*)&sB[1][r][sg] = *(const uint4*)(pBl + go);
        }
        __syncthreads();

        #pragma unroll
        for (int kk = 0; kk < 2; ++kk) {
            uint32_t ah[2][4], al[2][4];
            #pragma unroll
            for (int mf = 0; mf < 2; ++mf) {
                uint32_t off = (uint32_t)((wm + mf * 16 + aRow) * 40 + kk * 16 + aK) * 2;
                LDM4(ah[mf], baseA + off);
                LDM4(al[mf], baseA + 128 * 40 * 2 + off);
            }
            uint32_t bh[NFRAG][2], bl[NFRAG][2];
            #pragma unroll
            for (int np = 0; np < NFRAG / 2; ++np) {
                uint32_t off = (uint32_t)((wn + np * 16 + bRow) * 40 + kk * 16 + bK) * 2;
                uint32_t t[4];
                LDM4(t, baseB + off);
                bh[np*2][0] = t[0]; bh[np*2][1] = t[1]; bh[np*2+1][0] = t[2]; bh[np*2+1][1] = t[3];
                LDM4(t, baseB + TN * 40 * 2 + off);
                bl[np*2][0] = t[0]; bl[np*2][1] = t[1]; bl[np*2+1][0] = t[2]; bl[np*2+1][1] = t[3];
            }
            #pragma unroll
            for (int mf = 0; mf < 2; ++mf)
                #pragma unroll
                for (int nf = 0; nf < NFRAG; ++nf) {
                    MMA(acc[mf][nf], ah[mf], bh[nf]);
                    MMA(acc[mf][nf], ah[mf], bl[nf]);
                    MMA(acc[mf][nf], al[mf], bh[nf]);
                }
        }
        __syncthreads();
    }

    int rb = m0 + wm + (lane >> 2);
    int cb = n0 + wn + (lane & 3) * 2;
    #pragma unroll
    for (int mf = 0; mf < 2; ++mf)
        #pragma unroll
        for (int half = 0; half < 2; ++half) {
            long row = rb + mf * 16 + half * 8;
            #pragma unroll
            for (int nf = 0; nf < NFRAG; ++nf) {
                int cc = cb + nf * 8;
                float v0 = alpha * acc[mf][nf][half * 2 + 0];
                float v1 = alpha * acc[mf][nf][half * 2 + 1];
                if (BIAS) { v0 += bias[cc]; v1 += bias[cc + 1]; }
                long base = co + row * (long)ldc + cc;
                if (F32O) { C[base] = v0; C[base + 1] = v1; }
                if (PO) {
                    bf h0 = __float2bfloat16(v0), h1 = __float2bfloat16(v1);
                    __nv_bfloat162 hp; hp.x = h0; hp.y = h1;
                    __nv_bfloat162 lp;
                    lp.x = __float2bfloat16(v0 - __bfloat162float(h0));
                    lp.y = __float2bfloat16(v1 - __bfloat162float(h1));
                    *reinterpret_cast<__nv_bfloat162*>(Ch + base) = hp;
                    *reinterpret_cast<__nv_bfloat162*>(Cl + base) = lp;
                }
            }
        }
}

// ---------- fused flash attention with cp.async double buffering --------------
// A,K: [rows, 64] K-major hi/lo.  V: [BH][64][S] (d-major) hi/lo.
// Block: 128 q-rows, 8 warps x 16 rows. Col tiles of 64. Dynamic smem 72KB.
// Buffer layout (bf16 elems, per buffer 18432): Kh@0, Kl@4608, Vh@9216, Vl@13824.
template<bool CAUSAL, bool PAIRO, bool ACC>
__global__ void __launch_bounds__(256) fa_k(
    const bf* __restrict__ Ah, const bf* __restrict__ Al, int lda, long sAb, long sAh_,
    const bf* __restrict__ Kh, const bf* __restrict__ Kl, int ldk, long sKb, long sKh_,
    const bf* __restrict__ Vh, const bf* __restrict__ Vl, int S_,
    float* __restrict__ O, bf* __restrict__ Oh, bf* __restrict__ Ol,
    int ldo, long sOb, long sOh_, float scale)
{
    extern __shared__ __align__(16) bf dsm[];
    uint32_t sbase = smem_u32(dsm);

    int z = blockIdx.y, bb = z >> 3, hh = z & 7;
    int m0 = (int)(gridDim.x - 1 - blockIdx.x) * 128;   // heavy blocks first
    const bf* pAh = Ah + bb * sAb + hh * sAh_;
    const bf* pAl = Al + bb * sAb + hh * sAh_;
    const bf* pKh = Kh + bb * sKb + hh * sKh_;
    const bf* pKl = Kl + bb * sKb + hh * sKh_;
    const bf* pVh = Vh + (long)z * 64 * S_;
    const bf* pVl = Vl + (long)z * 64 * S_;
    long co = (long)bb * sOb + (long)hh * sOh_;

    int tid = threadIdx.x, lane = tid & 31, wid = tid >> 5;
    int wrow = wid * 16;

    // stage q block [128x64] hi/lo into buffer0 region
    #pragma unroll
    for (int i = 0; i < 4; ++i) {
        int q = tid + i * 256, r = q >> 3, ch = q & 7;
        long go = (long)(m0 + r) * lda + ch * 8;
        *(uint4*)&dsm[r * 72 + ch * 8]        = *(const uint4*)(pAh + go);
        *(uint4*)&dsm[9216 + r * 72 + ch * 8] = *(const uint4*)(pAl + go);
    }
    __syncthreads();

    int aRow = lane & 15, aK = (lane >> 4) * 8;
    int bRow = (lane & 7) + ((lane >> 4) & 1) * 8, bK = ((lane >> 3) & 1) * 8;
    uint32_t qh[4][4], ql[4][4];
    #pragma unroll
    for (int kk = 0; kk < 4; ++kk) {
        uint32_t off = (uint32_t)((wrow + aRow) * 72 + kk * 16 + aK) * 2;
        LDM4(qh[kk], sbase + off);
        LDM4(ql[kk], sbase + 9216 * 2 + off);
    }
    __syncthreads();

    float o[8][4];
    #pragma unroll
    for (int i = 0; i < 8; ++i)
        #pragma unroll
        for (int q = 0; q < 4; ++q) o[i][q] = 0.f;
    float mr0 = -INFINITY, mr1 = -INFINITY, l0 = 0.f, l1 = 0.f;

    int nt = CAUSAL ? ((m0 >> 6) + 2) : (S_ >> 6);
    int row0 = m0 + wrow + (lane >> 2);
    int pr = tid >> 3, pch = tid & 7;   // prefetch lane mapping (2 iters of 256)

    // prefetch tile 0 into buffer 0
    {
        int c0 = 0;
        #pragma unroll
        for (int i = 0; i < 2; ++i) {
            int r = pr + i * 32;
            long gk = (long)(c0 + r) * ldk + pch * 8;
            long gv = (long)r * S_ + c0 + pch * 8;
            uint32_t so = (uint32_t)(r * 72 + pch * 8) * 2;
            CPA(sbase + so,             pKh + gk);
            CPA(sbase + 4608*2  + so,   pKl + gk);
            CPA(sbase + 9216*2  + so,   pVh + gv);
            CPA(sbase + 13824*2 + so,   pVl + gv);
        }
        CPA_COMMIT();
    }

    for (int ct = 0; ct < nt; ++ct) {
        uint32_t bo = (uint32_t)(ct & 1) * 18432u * 2u;
        if (ct + 1 < nt) {
            uint32_t bn = (uint32_t)((ct + 1) & 1) * 18432u * 2u;
            int c1 = (ct + 1) << 6;
            #pragma unroll
            for (int i = 0; i < 2; ++i) {
                int r = pr + i * 32;
                long gk = (long)(c1 + r) * ldk + pch * 8;
                long gv = (long)r * S_ + c1 + pch * 8;
                uint32_t so = bn + (uint32_t)(r * 72 + pch * 8) * 2;
                CPA(sbase + so,             pKh + gk);
                CPA(sbase + 4608*2  + so,   pKl + gk);
                CPA(sbase + 9216*2  + so,   pVh + gv);
                CPA(sbase + 13824*2 + so,   pVl + gv);
            }
            CPA_COMMIT();
            asm volatile("cp.async.wait_group 1;");
        } else {
            asm volatile("cp.async.wait_group 0;");
        }
        __syncthreads();

        int c0 = ct << 6;
        float s[8][4];
        #pragma unroll
        for (int i = 0; i < 8; ++i)
            #pragma unroll
            for (int q = 0; q < 4; ++q) s[i][q] = 0.f;

        #pragma unroll
        for (int kk = 0; kk < 4; ++kk) {
            uint32_t kh[8][2], kl[8][2];
            #pragma unroll
            for (int np = 0; np < 4; ++np) {
                uint32_t off = bo + (uint32_t)((np * 16 + bRow) * 72 + kk * 16 + bK) * 2;
                uint32_t t[4];
                LDM4(t, sbase + off);
                kh[np*2][0] = t[0]; kh[np*2][1] = t[1]; kh[np*2+1][0] = t[2]; kh[np*2+1][1] = t[3];
                LDM4(t, sbase + 4608 * 2 + off);
                kl[np*2][0] = t[0]; kl[np*2][1] = t[1]; kl[np*2+1][0] = t[2]; kl[np*2+1][1] = t[3];
            }
            #pragma unroll
            for (int nf = 0; nf < 8; ++nf) {
                MMA(s[nf], qh[kk], kh[nf]);
                MMA(s[nf], qh[kk], kl[nf]);
                MMA(s[nf], ql[kk], kh[nf]);
            }
        }
        #pragma unroll
        for (int nf = 0; nf < 8; ++nf) {
            #pragma unroll
            for (int q = 0; q < 4; ++q) s[nf][q] *= scale;
        }
        if (CAUSAL && (c0 + 63 > m0 + wrow)) {
            #pragma unroll
            for (int nf = 0; nf < 8; ++nf) {
                int col = c0 + nf * 8 + (lane & 3) * 2;
                if (col     > row0)     s[nf][0] = -1e30f;
                if (col + 1 > row0)     s[nf][1] = -1e30f;
                if (col     > row0 + 8) s[nf][2] = -1e30f;
                if (col + 1 > row0 + 8) s[nf][3] = -1e30f;
            }
        }
        float t0 = -INFINITY, t1 = -INFINITY;
        #pragma unroll
        for (int nf = 0; nf < 8; ++nf) {
            t0 = fmaxf(t0, fmaxf(s[nf][0], s[nf][1]));
            t1 = fmaxf(t1, fmaxf(s[nf][2], s[nf][3]));
        }
        t0 = fmaxf(t0, __shfl_xor_sync(0xffffffffu, t0, 1));
        t0 = fmaxf(t0, __shfl_xor_sync(0xffffffffu, t0, 2));
        t1 = fmaxf(t1, __shfl_xor_sync(0xffffffffu, t1, 1));
        t1 = fmaxf(t1, __shfl_xor_sync(0xffffffffu, t1, 2));
        float mn0 = fmaxf(mr0, t0), mn1 = fmaxf(mr1, t1);
        float cr0 = __expf(mr0 - mn0), cr1 = __expf(mr1 - mn1);
        float sum0 = 0.f, sum1 = 0.f;
        #pragma unroll
        for (int nf = 0; nf < 8; ++nf) {
            s[nf][0] = __expf(s[nf][0] - mn0);
            s[nf][1] = __expf(s[nf][1] - mn0);
            s[nf][2] = __expf(s[nf][2] - mn1);
            s[nf][3] = __expf(s[nf][3] - mn1);
            sum0 += s[nf][0] + s[nf][1];
            sum1 += s[nf][2] + s[nf][3];
        }
        sum0 += __shfl_xor_sync(0xffffffffu, sum0, 1);
        sum0 += __shfl_xor_sync(0xffffffffu, sum0, 2);
        sum1 += __shfl_xor_sync(0xffffffffu, sum1, 1);
        sum1 += __shfl_xor_sync(0xffffffffu, sum1, 2);
        l0 = l0 * cr0 + sum0; l1 = l1 * cr1 + sum1;
        mr0 = mn0; mr1 = mn1;
        #pragma unroll
        for (int nf = 0; nf < 8; ++nf) {
            o[nf][0] *= cr0; o[nf][1] *= cr0; o[nf][2] *= cr1; o[nf][3] *= cr1;
        }
        #pragma unroll
        for (int kk2 = 0; kk2 < 4; ++kk2) {
            uint32_t Ph[4], Pl[4];
            {
                float a0 = s[2*kk2][0],   a1 = s[2*kk2][1];
                float a2 = s[2*kk2][2],   a3 = s[2*kk2][3];
                float a4 = s[2*kk2+1][0], a5 = s[2*kk2+1][1];
                float a6 = s[2*kk2+1][2], a7 = s[2*kk2+1][3];
                bf h0 = __float2bfloat16(a0), h1 = __float2bfloat16(a1);
                bf h2 = __float2bfloat16(a2), h3 = __float2bfloat16(a3);
                bf h4 = __float2bfloat16(a4), h5 = __float2bfloat16(a5);
                bf h6 = __float2bfloat16(a6), h7 = __float2bfloat16(a7);
                Ph[0] = packbf(__bfloat162float(h0), __bfloat162float(h1));
                Ph[1] = packbf(__bfloat162float(h2), __bfloat162float(h3));
                Ph[2] = packbf(__bfloat162float(h4), __bfloat162float(h5));
                Ph[3] = packbf(__bfloat162float(h6), __bfloat162float(h7));
                Pl[0] = packbf(a0 - __bfloat162float(h0), a1 - __bfloat162float(h1));
                Pl[1] = packbf(a2 - __bfloat162float(h2), a3 - __bfloat162float(h3));
                Pl[2] = packbf(a4 - __bfloat162float(h4), a5 - __bfloat162float(h5));
                Pl[3] = packbf(a6 - __bfloat162float(h6), a7 - __bfloat162float(h7));
            }
            uint32_t vh[8][2], vl[8][2];
            #pragma unroll
            for (int np = 0; np < 4; ++np) {
                uint32_t off = bo + (uint32_t)((np * 16 + bRow) * 72 + kk2 * 16 + bK) * 2;
                uint32_t t[4];
                LDM4(t, sbase + 9216 * 2 + off);
                vh[np*2][0] = t[0]; vh[np*2][1] = t[1]; vh[np*2+1][0] = t[2]; vh[np*2+1][1] = t[3];
                LDM4(t, sbase + 13824 * 2 + off);
                vl[np*2][0] = t[0]; vl[np*2][1] = t[1]; vl[np*2+1][0] = t[2]; vl[np*2+1][1] = t[3];
            }
            #pragma unroll
            for (int nf = 0; nf < 8; ++nf) {
                MMA(o[nf], Ph, vh[nf]);
                MMA(o[nf], Ph, vl[nf]);
                MMA(o[nf], Pl, vh[nf]);
            }
        }
        __syncthreads();
    }

    float inv0 = 1.f / l0, inv1 = 1.f / l1;
    #pragma unroll
    for (int nf = 0; nf < 8; ++nf) {
        int col = nf * 8 + (lane & 3) * 2;
        float v0 = o[nf][0] * inv0, v1 = o[nf][1] * inv0;
        float v2 = o[nf][2] * inv1, v3 = o[nf][3] * inv1;
        long b0 = co + (long)row0 * ldo + col;
        long b1 = co + (long)(row0 + 8) * ldo + col;
        if (ACC) { v0 += O[b0]; v1 += O[b0 + 1]; v2 += O[b1]; v3 += O[b1 + 1]; }
        O[b0] = v0; O[b0 + 1] = v1; O[b1] = v2; O[b1 + 1] = v3;
        if (PAIRO) {
            bf h0 = __float2bfloat16(v0), h1 = __float2bfloat16(v1);
            bf h2 = __float2bfloat16(v2), h3 = __float2bfloat16(v3);
            __nv_bfloat162 hp0; hp0.x = h0; hp0.y = h1;
            __nv_bfloat162 hp1; hp1.x = h2; hp1.y = h3;
            __nv_bfloat162 lp0, lp1;
            lp0.x = __float2bfloat16(v0 - __bfloat162float(h0));
            lp0.y = __float2bfloat16(v1 - __bfloat162float(h1));
            lp1.x = __float2bfloat16(v2 - __bfloat162float(h2));
            lp1.y = __float2bfloat16(v3 - __bfloat162float(h3));
            *reinterpret_cast<__nv_bfloat162*>(Oh + b0) = hp0;
            *reinterpret_cast<__nv_bfloat162*>(Ol + b0) = lp0;
            *reinterpret_cast<__nv_bfloat162*>(Oh + b1) = hp1;
            *reinterpret_cast<__nv_bfloat162*>(Ol + b1) = lp1;
        }
    }
}

// ---------- G^T = SCL^2 * (k_y^T q_y)^T per head : [BH,64,64] bf16 pair -------
__global__ void __launch_bounds__(256) g_k(const bf* __restrict__ qh, const bf* __restrict__ ql,
                                           bf* __restrict__ goh, bf* __restrict__ gol)
{
    int z = blockIdx.x, b = z >> 3, h = z & 7;
    long kyo = (long)b * Mv * 3 * Cv + (long)h * Dv + Cv;
    long qyo = (long)b * Mv * 3 * Cv + (long)h * Dv;
    __shared__ float sky[64][65], sqy[64][65];
    int tid = threadIdx.x;
    int d2 = tid & 63, gg = tid >> 6;
    float acc[16];
    #pragma unroll
    for (int i = 0; i < 16; ++i) acc[i] = 0.f;
    for (int m0 = 0; m0 < Mv; m0 += 64) {
        #pragma unroll
        for (int i = 0; i < 16; ++i) {
            int q = tid + i * 256;
            int mm = q >> 6, dd = q & 63;
            long ik = kyo + (long)(m0 + mm) * 3 * Cv + dd;
            long iq = qyo + (long)(m0 + mm) * 3 * Cv + dd;
            sky[mm][dd] = __bfloat162float(qh[ik]) + __bfloat162float(ql[ik]);
            sqy[mm][dd] = __bfloat162float(qh[iq]) + __bfloat162float(ql[iq]);
        }
        __syncthreads();
        for (int mm = 0; mm < 64; ++mm) {
            float qv = sqy[mm][d2];
            #pragma unroll
            for (int i = 0; i < 16; ++i)
                acc[i] += sky[mm][gg * 16 + i] * qv;
        }
        __syncthreads();
    }
    long base = (long)z * 4096 + (long)d2 * 64 + gg * 16;
    #pragma unroll
    for (int i = 0; i < 16; ++i) {
        float v = acc[i] * (SCL * SCL);
        bf hh = __float2bfloat16(v);
        goh[base + i] = hh;
        gol[base + i] = __float2bfloat16(v - __bfloat162float(hh));
    }
}

// ---------- small utility kernels ----------
__global__ void split_k(const float* __restrict__ in, bf* __restrict__ oh, bf* __restrict__ ol, long n) {
    long i = (long)blockIdx.x * 256 + threadIdx.x;
    if (i < n) {
        float v = in[i]; bf h = __float2bfloat16(v);
        oh[i] = h; ol[i] = __float2bfloat16(v - __bfloat162float(h));
    }
}
__global__ void splitT_k(const float* __restrict__ in, bf* __restrict__ oh, bf* __restrict__ ol, int Kd, int Nd) {
    long i = (long)blockIdx.x * 256 + threadIdx.x;
    if (i < (long)Kd * Nd) {
        int n = (int)(i / Kd), k = (int)(i % Kd);
        float v = in[(long)k * Nd + n]; bf h = __float2bfloat16(v);
        oh[i] = h; ol[i] = __float2bfloat16(v - __bfloat162float(h));
    }
}
__global__ void vT_k(const bf* __restrict__ ih, const bf* __restrict__ il,
                     bf* __restrict__ oh, bf* __restrict__ ol, int L) {
    int z = blockIdx.y, b = z / Hv, h = z % Hv;
    long iof = (long)b * L * 3 * Cv + (long)h * Dv + 2 * Cv;
    long oof = (long)z * Dv * L;
    int idx = blockIdx.x * 256 + threadIdx.x;
    int d = idx / L, l = idx % L;
    long ii = iof + (long)l * 3 * Cv + d;
    oh[oof + idx] = ih[ii]; ol[oof + idx] = il[ii];
}
__global__ void gate_k(const float* __restrict__ t1, const float* __restrict__ t2,
                       const float* __restrict__ cv, const float* __restrict__ sv,
                       bf* __restrict__ oh, bf* __restrict__ ol, long n) {
    long i = (long)blockIdx.x * 256 + threadIdx.x;
    if (i < n) {
        float g1 = 1.f / (1.f + __expf(-t1[i]));
        float g2 = 1.f / (1.f + __expf(-t2[i]));
        float v = g1 * cv[i] + g2 * sv[i];
        bf h = __float2bfloat16(v);
        oh[i] = h; ol[i] = __float2bfloat16(v - __bfloat162float(h));
    }
}

// ------------------------------------------------------------------------------
extern "C" void kernel_launch(void* const* d_in, const int* in_sizes, int n_in,
                              void* d_out, int out_size)
{
    const float* x      = (const float*)d_in[0];
    const float* y      = (const float*)d_in[1];
    const float* Wqkv_x = (const float*)d_in[3];
    const float* bqkv_x = (const float*)d_in[4];
    const float* Wqkv_y = (const float*)d_in[5];
    const float* bqkv_y = (const float*)d_in[6];
    const float* Wgs    = (const float*)d_in[7];
    const float* bgs    = (const float*)d_in[8];
    const float* Wgc    = (const float*)d_in[9];
    const float* bgc    = (const float*)d_in[10];
    const float* Wp     = (const float*)d_in[11];
    const float* bp     = (const float*)d_in[12];
    float* out = (float*)d_out;

    bf *gh, *gl; float* gf;
    cudaGetSymbolAddress((void**)&gh, g_h);
    cudaGetSymbolAddress((void**)&gl, g_l);
    cudaGetSymbolAddress((void**)&gf, g_f);

    const int FASM = 2 * 18432 * 2;   // 73728 B dynamic smem
    cudaFuncSetAttribute((const void*)fa_k<false,false,false>, cudaFuncAttributeMaxDynamicSharedMemorySize, FASM);
    cudaFuncSetAttribute((const void*)fa_k<true,true,true>,   cudaFuncAttributeMaxDynamicSharedMemorySize, FASM);
    cudaFuncSetAttribute((const void*)fa_k<true,true,false>,  cudaFuncAttributeMaxDynamicSharedMemorySize, FASM);

    dim3 blk(256);
    long nTC = (long)BBv * Tv * Cv;

    // input / weight splits
    split_k<<<(unsigned)((nTC + 255) / 256), blk>>>(x, gh + oXB, gl + oXB, nTC);
    split_k<<<(unsigned)((BBv*Mv*Cv + 255) / 256), blk>>>(y, gh + oYB, gl + oYB, (long)BBv*Mv*Cv);
    splitT_k<<<(unsigned)((Cv*3*Cv + 255) / 256), blk>>>(Wqkv_x, gh + oWQX, gl + oWQX, Cv, 3*Cv);
    splitT_k<<<(unsigned)((Cv*3*Cv + 255) / 256), blk>>>(Wqkv_y, gh + oWQY, gl + oWQY, Cv, 3*Cv);
    splitT_k<<<(unsigned)((Cv*Cv + 255) / 256), blk>>>(Wgs, gh + oWGS, gl + oWGS, Cv, Cv);
    splitT_k<<<(unsigned)((Cv*Cv + 255) / 256), blk>>>(Wgc, gh + oWGC, gl + oWGC, Cv, Cv);
    splitT_k<<<(unsigned)((Cv*Cv + 255) / 256), blk>>>(Wp,  gh + oWP,  gl + oWP,  Cv, Cv);

    // qkv projections (pair out)
    hg<128,false,true,true><<<dim3(12,32,1), blk>>>(
        gh+oXB, gl+oXB, Cv, 0,0, gh+oWQX, gl+oWQX, Cv, 0,0,
        nullptr, gh+oQKVX, gl+oQKVX, 3*Cv, 0,0, bqkv_x, Cv, 1, 1.0f);
    hg<128,false,true,true><<<dim3(12,8,1), blk>>>(
        gh+oYB, gl+oYB, Cv, 0,0, gh+oWQY, gl+oWQY, Cv, 0,0,
        nullptr, gh+oQKVY, gl+oQKVY, 3*Cv, 0,0, bqkv_y, Cv, 1, 1.0f);

    // v transposes -> [BH][64][L]
    vT_k<<<dim3(Dv*Tv/256, BHv), blk>>>(gh+oQKVX, gl+oQKVX, gh+oVXT, gl+oVXT, Tv);
    vT_k<<<dim3(Dv*Mv/256, BHv), blk>>>(gh+oQKVY, gl+oQKVY, gh+oVYT, gl+oVYT, Mv);

    // G^T = SCL^2 * (k_y^T @ q_y)^T  [BH,64,64]
    g_k<<<BHv, blk>>>(gh+oQKVY, gl+oQKVY, gh+oGT, gl+oGT);

    // qxG = q_x @ G  [BH,T,64]  (pair out)
    hg<64,false,true,false><<<dim3(1,16,16), blk>>>(
        gh+oQKVX, gl+oQKVX, 3*Cv, (long)Tv*3*Cv, (long)Dv,
        gh+oGT, gl+oGT, 64, (long)Hv*Dv*Dv, (long)Dv*Dv,
        nullptr, gh+oQXG, gl+oQXG, Dv, (long)Hv*Tv*Dv, (long)Tv*Dv, nullptr, Dv, Hv, 1.0f);

    // cval1 = softmax(q_x k_y^T) v_y  (fused, non-causal, S=512)
    fa_k<false,false,false><<<dim3(16,16), blk, FASM>>>(
        gh+oQKVX, gl+oQKVX, 3*Cv, (long)Tv*3*Cv, (long)Dv,
        gh+oQKVY+Cv, gl+oQKVY+Cv, 3*Cv, (long)Mv*3*Cv, (long)Dv,
        gh+oVYT, gl+oVYT, Mv,
        gf+fC1, nullptr, nullptr, Cv, (long)Tv*Cv, (long)Dv, SCL);

    // cval = cval1 + softmax_causal(qxG k_x^T) v_x  (fused, ACC + pair out)
    fa_k<true,true,true><<<dim3(16,16), blk, FASM>>>(
        gh+oQXG, gl+oQXG, Dv, (long)Hv*Tv*Dv, (long)Tv*Dv,
        gh+oQKVX+Cv, gl+oQKVX+Cv, 3*Cv, (long)Tv*3*Cv, (long)Dv,
        gh+oVXT, gl+oVXT, Tv,
        gf+fC1, gh+oCV, gl+oCV, Cv, (long)Tv*Cv, (long)Dv, SCL);

    // sval = softmax_causal(q_x k_x^T) v_x  (fused, pair out)
    fa_k<true,true,false><<<dim3(16,16), blk, FASM>>>(
        gh+oQKVX, gl+oQKVX, 3*Cv, (long)Tv*3*Cv, (long)Dv,
        gh+oQKVX+Cv, gl+oQKVX+Cv, 3*Cv, (long)Tv*3*Cv, (long)Dv,
        gh+oVXT, gl+oVXT, Tv,
        gf+fSV, gh+oSV, gl+oSV, Cv, (long)Tv*Cv, (long)Dv, SCL);

    // gates
    hg<128,true,false,true><<<dim3(4,32,1), blk>>>(
        gh+oSV, gl+oSV, Cv, 0,0, gh+oWGS, gl+oWGS, Cv, 0,0,
        gf+fT1, nullptr, nullptr, Cv, 0,0, bgs, Cv, 1, 1.0f);
    hg<128,true,false,true><<<dim3(4,32,1), blk>>>(
        gh+oCV, gl+oCV, Cv, 0,0, gh+oWGC, gl+oWGC, Cv, 0,0,
        gf+fT2, nullptr, nullptr, Cv, 0,0, bgc, Cv, 1, 1.0f);

    gate_k<<<(unsigned)((nTC + 255) / 256), blk>>>(gf+fT1, gf+fT2, gf+fC1, gf+fSV, gh+oT3, gl+oT3, nTC);

    // out = t3 @ Wp + bp
    hg<128,true,false,true><<<dim3(4,32,1), blk>>>(
        gh+oT3, gl+oT3, Cv, 0,0, gh+oWP, gl+oWP, Cv, 0,0,
        out, nullptr, nullptr, Cv, 0,0, bp, Cv, 1, 1.0f);
}

// round 10
// speedup vs baseline: 9.7073x; 1.1024x over previous
#include <cuda_runtime.h>
#include <cuda_bf16.h>
#include <cstdint>
#include <math.h>

#define BBv 2
#define Tv 2048
#define Mv 512
#define Cv 512
#define Hv 8
#define Dv 64
#define BHv 16
#define SCL 0.125f
typedef __nv_bfloat16 bf;

// ---------- bf16 pair pool offsets ----------
constexpr long oXB   = 0;
constexpr long oYB   = oXB   + (long)BBv*Tv*Cv;
constexpr long oWQX  = oYB   + (long)BBv*Mv*Cv;
constexpr long oWQY  = oWQX  + (long)Cv*3*Cv;
constexpr long oWGS  = oWQY  + (long)Cv*3*Cv;
constexpr long oWGC  = oWGS  + (long)Cv*Cv;
constexpr long oWP   = oWGC  + (long)Cv*Cv;
constexpr long oQKVX = oWP   + (long)Cv*Cv;
constexpr long oQKVY = oQKVX + (long)BBv*Tv*3*Cv;
constexpr long oQXG  = oQKVY + (long)BBv*Mv*3*Cv;
constexpr long oGT   = oQXG  + (long)BHv*Tv*Dv;
constexpr long oSV   = oGT   + (long)BHv*Dv*Dv;
constexpr long oCV   = oSV   + (long)BBv*Tv*Cv;
constexpr long oT3   = oCV   + (long)BBv*Tv*Cv;
constexpr long NBF   = oT3   + (long)BBv*Tv*Cv;
// ---------- fp32 pool ----------
constexpr long fC1 = 0;
constexpr long fSV = fC1 + (long)BBv*Tv*Cv;
constexpr long fT1 = fSV + (long)BBv*Tv*Cv;
constexpr long fT2 = fT1 + (long)BBv*Tv*Cv;
constexpr long NF_ = fT2 + (long)BBv*Tv*Cv;

__device__ bf    g_h[NBF];
__device__ bf    g_l[NBF];
__device__ float g_f[NF_];

// ---------- helpers ----------
__device__ __forceinline__ uint32_t smem_u32(const void* p) {
    uint32_t a;
    asm("{ .reg .u64 t; cvta.to.shared.u64 t, %1; cvt.u32.u64 %0, t; }" : "=r"(a) : "l"(p));
    return a;
}
#define LDM4(r, addr) asm volatile( \
    "ldmatrix.sync.aligned.m8n8.x4.shared.b16 {%0,%1,%2,%3}, [%4];" \
    : "=r"((r)[0]), "=r"((r)[1]), "=r"((r)[2]), "=r"((r)[3]) : "r"(addr))
#define LDM4T(r, addr) asm volatile( \
    "ldmatrix.sync.aligned.m8n8.x4.trans.shared.b16 {%0,%1,%2,%3}, [%4];" \
    : "=r"((r)[0]), "=r"((r)[1]), "=r"((r)[2]), "=r"((r)[3]) : "r"(addr))
#define MMA(c, a, b) asm volatile( \
    "mma.sync.aligned.m16n8k16.row.col.f32.bf16.bf16.f32 " \
    "{%0,%1,%2,%3}, {%4,%5,%6,%7}, {%8,%9}, {%0,%1,%2,%3};" \
    : "+f"((c)[0]), "+f"((c)[1]), "+f"((c)[2]), "+f"((c)[3]) \
    : "r"((a)[0]), "r"((a)[1]), "r"((a)[2]), "r"((a)[3]), "r"((b)[0]), "r"((b)[1]))
#define CPA(sa, ga) asm volatile("cp.async.cg.shared.global [%0], [%1], 16;" :: "r"(sa), "l"(ga))
#define CPA_COMMIT() asm volatile("cp.async.commit_group;")

__device__ __forceinline__ uint32_t packbf(float a, float b) {
    __nv_bfloat162 t; t.x = __float2bfloat16(a); t.y = __float2bfloat16(b);
    return *reinterpret_cast<uint32_t*>(&t);
}

// ---------- HMMA split-bf16 GEMM: C = alpha*(A@B^T) (+bias) -------------------
template<int TN, bool F32O, bool PO, bool BIAS>
__global__ void __launch_bounds__(256) hg(
    const bf* __restrict__ Ah, const bf* __restrict__ Al, int lda, long sAb, long sAh_,
    const bf* __restrict__ Bh, const bf* __restrict__ Bl, int ldb, long sBb, long sBh_,
    float* __restrict__ C, bf* __restrict__ Ch, bf* __restrict__ Cl, int ldc, long sCb, long sCh_,
    const float* __restrict__ bias, int K, int Hn, float alpha)
{
    constexpr int NFRAG = TN / 16;
    int m0 = blockIdx.y * 128, n0 = blockIdx.x * TN;
    int z = blockIdx.z, bb = z / Hn, hh = z - bb * Hn;
    const bf* pAh = Ah + bb * sAb + hh * sAh_;
    const bf* pAl = Al + bb * sAb + hh * sAh_;
    const bf* pBh = Bh + bb * sBb + hh * sBh_;
    const bf* pBl = Bl + bb * sBb + hh * sBh_;
    long co = bb * sCb + hh * sCh_;

    __shared__ bf sA[2][128][40];
    __shared__ bf sB[2][TN][40];
    uint32_t baseA = smem_u32(&sA[0][0][0]);
    uint32_t baseB = smem_u32(&sB[0][0][0]);

    int tid = threadIdx.x, lane = tid & 31, wid = tid >> 5;
    int wm = (wid & 3) * 32, wn = (wid >> 2) * (TN / 2);

    float acc[2][NFRAG][4];
    #pragma unroll
    for (int i = 0; i < 2; ++i)
        #pragma unroll
        for (int j = 0; j < NFRAG; ++j)
            #pragma unroll
            for (int q = 0; q < 4; ++q) acc[i][j][q] = 0.f;

    int kst = K >> 5;
    int aRow = (lane & 15), aK = (lane >> 4) * 8;
    int bRow = (lane & 7) + ((lane >> 4) & 1) * 8, bK = ((lane >> 3) & 1) * 8;

    for (int s = 0; s < kst; ++s) {
        int k0 = s << 5;
        #pragma unroll
        for (int i = 0; i < 2; ++i) {
            int q = tid + i * 256, r = q >> 2, sg = (q & 3) * 8;
            long go = (long)(m0 + r) * lda + k0 + sg;
            *(uint4*)&sA[0][r][sg] = *(const uint4*)(pAh + go);
            *(uint4*)&sA[1][r][sg] = *(const uint4*)(pAl + go);
        }
        #pragma unroll
        for (int i = 0; i < TN / 64; ++i) {
            int q = tid + i * 256, r = q >> 2, sg = (q & 3) * 8;
            long go = (long)(n0 + r) * ldb + k0 + sg;
            *(uint4*)&sB[0][r][sg] = *(const uint4*)(pBh + go);
            *(uint4*)&sB[1][r][sg] = *(const uint4*)(pBl + go);
        }
        __syncthreads();

        #pragma unroll
        for (int kk = 0; kk < 2; ++kk) {
            uint32_t ah[2][4], al[2][4];
            #pragma unroll
            for (int mf = 0; mf < 2; ++mf) {
                uint32_t off = (uint32_t)((wm + mf * 16 + aRow) * 40 + kk * 16 + aK) * 2;
                LDM4(ah[mf], baseA + off);
                LDM4(al[mf], baseA + 128 * 40 * 2 + off);
            }
            uint32_t bh[NFRAG][2], bl[NFRAG][2];
            #pragma unroll
            for (int np = 0; np < NFRAG / 2; ++np) {
                uint32_t off = (uint32_t)((wn + np * 16 + bRow) * 40 + kk * 16 + bK) * 2;
                uint32_t t[4];
                LDM4(t, baseB + off);
                bh[np*2][0] = t[0]; bh[np*2][1] = t[1]; bh[np*2+1][0] = t[2]; bh[np*2+1][1] = t[3];
                LDM4(t, baseB + TN * 40 * 2 + off);
                bl[np*2][0] = t[0]; bl[np*2][1] = t[1]; bl[np*2+1][0] = t[2]; bl[np*2+1][1] = t[3];
            }
            #pragma unroll
            for (int mf = 0; mf < 2; ++mf)
                #pragma unroll
                for (int nf = 0; nf < NFRAG; ++nf) {
                    MMA(acc[mf][nf], ah[mf], bh[nf]);
                    MMA(acc[mf][nf], ah[mf], bl[nf]);
                    MMA(acc[mf][nf], al[mf], bh[nf]);
                }
        }
        __syncthreads();
    }

    int rb = m0 + wm + (lane >> 2);
    int cb = n0 + wn + (lane & 3) * 2;
    #pragma unroll
    for (int mf = 0; mf < 2; ++mf)
        #pragma unroll
        for (int half = 0; half < 2; ++half) {
            long row = rb + mf * 16 + half * 8;
            #pragma unroll
            for (int nf = 0; nf < NFRAG; ++nf) {
                int cc = cb + nf * 8;
                float v0 = alpha * acc[mf][nf][half * 2 + 0];
                float v1 = alpha * acc[mf][nf][half * 2 + 1];
                if (BIAS) { v0 += bias[cc]; v1 += bias[cc + 1]; }
                long base = co + row * (long)ldc + cc;
                if (F32O) { C[base] = v0; C[base + 1] = v1; }
                if (PO) {
                    bf h0 = __float2bfloat16(v0), h1 = __float2bfloat16(v1);
                    __nv_bfloat162 hp; hp.x = h0; hp.y = h1;
                    __nv_bfloat162 lp;
                    lp.x = __float2bfloat16(v0 - __bfloat162float(h0));
                    lp.y = __float2bfloat16(v1 - __bfloat162float(h1));
                    *reinterpret_cast<__nv_bfloat162*>(Ch + base) = hp;
                    *reinterpret_cast<__nv_bfloat162*>(Cl + base) = lp;
                }
            }
        }
}

// ---------- shared attention tile step (scores -> online softmax -> PV) -------
// smem buffer at bo: Kh@0, Kl@4608, V(h)@9216, V(l)@13824 (elems; V stored [s][d]).
template<bool CAUSAL>
__device__ __forceinline__ void attn_tile(
    uint32_t sbase, uint32_t bo,
    uint32_t (&qh)[4][4], uint32_t (&ql)[4][4],
    float (&o)[8][4], float& mr0, float& mr1, float& l0, float& l1,
    int c0, int row0, int diagRow, float scale, int lane)
{
    int bRow = (lane & 7) + ((lane >> 4) & 1) * 8, bK = ((lane >> 3) & 1) * 8;
    int vRow = (lane & 7) + ((lane >> 3) & 1) * 8, vN = ((lane >> 4) & 1) * 8;

    float s[8][4];
    #pragma unroll
    for (int i = 0; i < 8; ++i)
        #pragma unroll
        for (int q = 0; q < 4; ++q) s[i][q] = 0.f;

    #pragma unroll
    for (int kk = 0; kk < 4; ++kk) {
        uint32_t kh[8][2], kl[8][2];
        #pragma unroll
        for (int np = 0; np < 4; ++np) {
            uint32_t off = bo + (uint32_t)((np * 16 + bRow) * 72 + kk * 16 + bK) * 2;
            uint32_t t[4];
            LDM4(t, sbase + off);
            kh[np*2][0] = t[0]; kh[np*2][1] = t[1]; kh[np*2+1][0] = t[2]; kh[np*2+1][1] = t[3];
            LDM4(t, sbase + 4608 * 2 + off);
            kl[np*2][0] = t[0]; kl[np*2][1] = t[1]; kl[np*2+1][0] = t[2]; kl[np*2+1][1] = t[3];
        }
        #pragma unroll
        for (int nf = 0; nf < 8; ++nf) {
            MMA(s[nf], qh[kk], kh[nf]);
            MMA(s[nf], qh[kk], kl[nf]);
            MMA(s[nf], ql[kk], kh[nf]);
        }
    }
    #pragma unroll
    for (int nf = 0; nf < 8; ++nf) {
        #pragma unroll
        for (int q = 0; q < 4; ++q) s[nf][q] *= scale;
    }
    if (CAUSAL && (c0 + 63 > diagRow)) {
        #pragma unroll
        for (int nf = 0; nf < 8; ++nf) {
            int col = c0 + nf * 8 + (lane & 3) * 2;
            if (col     > row0)     s[nf][0] = -1e30f;
            if (col + 1 > row0)     s[nf][1] = -1e30f;
            if (col     > row0 + 8) s[nf][2] = -1e30f;
            if (col + 1 > row0 + 8) s[nf][3] = -1e30f;
        }
    }
    float t0 = -INFINITY, t1 = -INFINITY;
    #pragma unroll
    for (int nf = 0; nf < 8; ++nf) {
        t0 = fmaxf(t0, fmaxf(s[nf][0], s[nf][1]));
        t1 = fmaxf(t1, fmaxf(s[nf][2], s[nf][3]));
    }
    t0 = fmaxf(t0, __shfl_xor_sync(0xffffffffu, t0, 1));
    t0 = fmaxf(t0, __shfl_xor_sync(0xffffffffu, t0, 2));
    t1 = fmaxf(t1, __shfl_xor_sync(0xffffffffu, t1, 1));
    t1 = fmaxf(t1, __shfl_xor_sync(0xffffffffu, t1, 2));
    float mn0 = fmaxf(mr0, t0), mn1 = fmaxf(mr1, t1);
    float cr0 = __expf(mr0 - mn0), cr1 = __expf(mr1 - mn1);
    float sum0 = 0.f, sum1 = 0.f;
    #pragma unroll
    for (int nf = 0; nf < 8; ++nf) {
        s[nf][0] = __expf(s[nf][0] - mn0);
        s[nf][1] = __expf(s[nf][1] - mn0);
        s[nf][2] = __expf(s[nf][2] - mn1);
        s[nf][3] = __expf(s[nf][3] - mn1);
        sum0 += s[nf][0] + s[nf][1];
        sum1 += s[nf][2] + s[nf][3];
    }
    sum0 += __shfl_xor_sync(0xffffffffu, sum0, 1);
    sum0 += __shfl_xor_sync(0xffffffffu, sum0, 2);
    sum1 += __shfl_xor_sync(0xffffffffu, sum1, 1);
    sum1 += __shfl_xor_sync(0xffffffffu, sum1, 2);
    l0 = l0 * cr0 + sum0; l1 = l1 * cr1 + sum1;
    mr0 = mn0; mr1 = mn1;
    #pragma unroll
    for (int nf = 0; nf < 8; ++nf) {
        o[nf][0] *= cr0; o[nf][1] *= cr0; o[nf][2] *= cr1; o[nf][3] *= cr1;
    }
    #pragma unroll
    for (int kk2 = 0; kk2 < 4; ++kk2) {
        uint32_t Ph[4], Pl[4];
        {
            float a0 = s[2*kk2][0],   a1 = s[2*kk2][1];
            float a2 = s[2*kk2][2],   a3 = s[2*kk2][3];
            float a4 = s[2*kk2+1][0], a5 = s[2*kk2+1][1];
            float a6 = s[2*kk2+1][2], a7 = s[2*kk2+1][3];
            bf h0 = __float2bfloat16(a0), h1 = __float2bfloat16(a1);
            bf h2 = __float2bfloat16(a2), h3 = __float2bfloat16(a3);
            bf h4 = __float2bfloat16(a4), h5 = __float2bfloat16(a5);
            bf h6 = __float2bfloat16(a6), h7 = __float2bfloat16(a7);
            Ph[0] = packbf(__bfloat162float(h0), __bfloat162float(h1));
            Ph[1] = packbf(__bfloat162float(h2), __bfloat162float(h3));
            Ph[2] = packbf(__bfloat162float(h4), __bfloat162float(h5));
            Ph[3] = packbf(__bfloat162float(h6), __bfloat162float(h7));
            Pl[0] = packbf(a0 - __bfloat162float(h0), a1 - __bfloat162float(h1));
            Pl[1] = packbf(a2 - __bfloat162float(h2), a3 - __bfloat162float(h3));
            Pl[2] = packbf(a4 - __bfloat162float(h4), a5 - __bfloat162float(h5));
            Pl[3] = packbf(a6 - __bfloat162float(h6), a7 - __bfloat162float(h7));
        }
        uint32_t vh[8][2], vl[8][2];
        #pragma unroll
        for (int np = 0; np < 4; ++np) {
            uint32_t off = bo + (uint32_t)((kk2 * 16 + vRow) * 72 + np * 16 + vN) * 2;
            uint32_t t[4];
            LDM4T(t, sbase + 9216 * 2 + off);
            vh[np*2][0] = t[0]; vh[np*2][1] = t[1]; vh[np*2+1][0] = t[2]; vh[np*2+1][1] = t[3];
            LDM4T(t, sbase + 13824 * 2 + off);
            vl[np*2][0] = t[0]; vl[np*2][1] = t[1]; vl[np*2+1][0] = t[2]; vl[np*2+1][1] = t[3];
        }
        #pragma unroll
        for (int nf = 0; nf < 8; ++nf) {
            MMA(o[nf], Ph, vh[nf]);
            MMA(o[nf], Ph, vl[nf]);
            MMA(o[nf], Pl, vh[nf]);
        }
    }
}

// prefetch one K/V tile (V loaded directly from qkv row-major [s][d])
__device__ __forceinline__ void kv_prefetch(
    uint32_t sbase, uint32_t bn, int c0,
    const bf* pKh, const bf* pKl, int ldk,
    const bf* pVh, const bf* pVl, int ldv, int tid)
{
    int pr = tid >> 3, pch = tid & 7;
    #pragma unroll
    for (int i = 0; i < 2; ++i) {
        int r = pr + i * 32;
        long gk = (long)(c0 + r) * ldk + pch * 8;
        long gv = (long)(c0 + r) * ldv + pch * 8;
        uint32_t so = bn + (uint32_t)(r * 72 + pch * 8) * 2;
        CPA(sbase + so,             pKh + gk);
        CPA(sbase + 4608*2  + so,   pKl + gk);
        CPA(sbase + 9216*2  + so,   pVh + gv);
        CPA(sbase + 13824*2 + so,   pVl + gv);
    }
    CPA_COMMIT();
}

// ---------- single-Q flash (non-causal; used for cval1), f32 out --------------
__global__ void __launch_bounds__(256) fa_k(
    const bf* __restrict__ Ah, const bf* __restrict__ Al, int lda, long sAb, long sAh_,
    const bf* __restrict__ Kh, const bf* __restrict__ Kl, int ldk, long sKb, long sKh_,
    const bf* __restrict__ Vh, const bf* __restrict__ Vl, int ldv, long sVb, long sVh_,
    int S_, float* __restrict__ O, int ldo, long sOb, long sOh_, float scale)
{
    extern __shared__ __align__(16) bf dsm[];
    uint32_t sbase = smem_u32(dsm);

    int z = blockIdx.y, bb = z >> 3, hh = z & 7;
    int m0 = (int)blockIdx.x * 128;
    const bf* pAh = Ah + bb * sAb + hh * sAh_;
    const bf* pAl = Al + bb * sAb + hh * sAh_;
    const bf* pKh = Kh + bb * sKb + hh * sKh_;
    const bf* pKl = Kl + bb * sKb + hh * sKh_;
    const bf* pVh = Vh + bb * sVb + hh * sVh_;
    const bf* pVl = Vl + bb * sVb + hh * sVh_;
    long co = (long)bb * sOb + (long)hh * sOh_;

    int tid = threadIdx.x, lane = tid & 31, wid = tid >> 5;
    int wrow = wid * 16;

    #pragma unroll
    for (int i = 0; i < 4; ++i) {
        int q = tid + i * 256, r = q >> 3, ch = q & 7;
        long go = (long)(m0 + r) * lda + ch * 8;
        *(uint4*)&dsm[r * 72 + ch * 8]        = *(const uint4*)(pAh + go);
        *(uint4*)&dsm[9216 + r * 72 + ch * 8] = *(const uint4*)(pAl + go);
    }
    __syncthreads();
    int aRow = lane & 15, aK = (lane >> 4) * 8;
    uint32_t qh[4][4], ql[4][4];
    #pragma unroll
    for (int kk = 0; kk < 4; ++kk) {
        uint32_t off = (uint32_t)((wrow + aRow) * 72 + kk * 16 + aK) * 2;
        LDM4(qh[kk], sbase + off);
        LDM4(ql[kk], sbase + 9216 * 2 + off);
    }
    __syncthreads();

    float o[8][4];
    #pragma unroll
    for (int i = 0; i < 8; ++i)
        #pragma unroll
        for (int q = 0; q < 4; ++q) o[i][q] = 0.f;
    float mr0 = -INFINITY, mr1 = -INFINITY, l0 = 0.f, l1 = 0.f;

    int nt = S_ >> 6;
    int row0 = m0 + wrow + (lane >> 2);

    kv_prefetch(sbase, 0, 0, pKh, pKl, ldk, pVh, pVl, ldv, tid);

    for (int ct = 0; ct < nt; ++ct) {
        uint32_t bo = (uint32_t)(ct & 1) * 18432u * 2u;
        if (ct + 1 < nt) {
            kv_prefetch(sbase, (uint32_t)((ct + 1) & 1) * 18432u * 2u, (ct + 1) << 6,
                        pKh, pKl, ldk, pVh, pVl, ldv, tid);
            asm volatile("cp.async.wait_group 1;");
        } else {
            asm volatile("cp.async.wait_group 0;");
        }
        __syncthreads();
        attn_tile<false>(sbase, bo, qh, ql, o, mr0, mr1, l0, l1,
                         ct << 6, row0, 0, scale, lane);
        __syncthreads();
    }

    float inv0 = 1.f / l0, inv1 = 1.f / l1;
    #pragma unroll
    for (int nf = 0; nf < 8; ++nf) {
        int col = nf * 8 + (lane & 3) * 2;
        long b0 = co + (long)row0 * ldo + col;
        long b1 = co + (long)(row0 + 8) * ldo + col;
        O[b0] = o[nf][0] * inv0; O[b0 + 1] = o[nf][1] * inv0;
        O[b1] = o[nf][2] * inv1; O[b1 + 1] = o[nf][3] * inv1;
    }
}

// ---------- dual-Q causal flash: cval2 (ACC into O1) + sval, shared K/V -------
__global__ void __launch_bounds__(256) fa2_k(
    const bf* __restrict__ A1h, const bf* __restrict__ A1l, int lda1, long sA1b, long sA1h,
    const bf* __restrict__ A2h, const bf* __restrict__ A2l, int lda2, long sA2b, long sA2h,
    const bf* __restrict__ Kh, const bf* __restrict__ Kl, int ldk, long sKb, long sKh_,
    const bf* __restrict__ Vh, const bf* __restrict__ Vl, int ldv, long sVb, long sVh_,
    float* __restrict__ O1, bf* __restrict__ O1h, bf* __restrict__ O1l,
    float* __restrict__ O2, bf* __restrict__ O2h, bf* __restrict__ O2l,
    int ldo, long sOb, long sOh_, float scale)
{
    extern __shared__ __align__(16) bf dsm[];
    uint32_t sbase = smem_u32(dsm);

    int z = blockIdx.y, bb = z >> 3, hh = z & 7;
    int m0 = (int)(gridDim.x - 1 - blockIdx.x) * 128;   // heavy blocks first
    const bf* pKh = Kh + bb * sKb + hh * sKh_;
    const bf* pKl = Kl + bb * sKb + hh * sKh_;
    const bf* pVh = Vh + bb * sVb + hh * sVh_;
    const bf* pVl = Vl + bb * sVb + hh * sVh_;
    long co = (long)bb * sOb + (long)hh * sOh_;

    int tid = threadIdx.x, lane = tid & 31, wid = tid >> 5;
    int wrow = wid * 16;
    int aRow = lane & 15, aK = (lane >> 4) * 8;
    uint32_t q1h[4][4], q1l[4][4], q2h[4][4], q2l[4][4];

    // stage Q1 then Q2 through buffer region
    {
        const bf* p1h = A1h + bb * sA1b + hh * sA1h;
        const bf* p1l = A1l + bb * sA1b + hh * sA1h;
        #pragma unroll
        for (int i = 0; i < 4; ++i) {
            int q = tid + i * 256, r = q >> 3, ch = q & 7;
            long go = (long)(m0 + r) * lda1 + ch * 8;
            *(uint4*)&dsm[r * 72 + ch * 8]        = *(const uint4*)(p1h + go);
            *(uint4*)&dsm[9216 + r * 72 + ch * 8] = *(const uint4*)(p1l + go);
        }
        __syncthreads();
        #pragma unroll
        for (int kk = 0; kk < 4; ++kk) {
            uint32_t off = (uint32_t)((wrow + aRow) * 72 + kk * 16 + aK) * 2;
            LDM4(q1h[kk], sbase + off);
            LDM4(q1l[kk], sbase + 9216 * 2 + off);
        }
        __syncthreads();
        const bf* p2h = A2h + bb * sA2b + hh * sA2h;
        const bf* p2l = A2l + bb * sA2b + hh * sA2h;
        #pragma unroll
        for (int i = 0; i < 4; ++i) {
            int q = tid + i * 256, r = q >> 3, ch = q & 7;
            long go = (long)(m0 + r) * lda2 + ch * 8;
            *(uint4*)&dsm[r * 72 + ch * 8]        = *(const uint4*)(p2h + go);
            *(uint4*)&dsm[9216 + r * 72 + ch * 8] = *(const uint4*)(p2l + go);
        }
        __syncthreads();
        #pragma unroll
        for (int kk = 0; kk < 4; ++kk) {
            uint32_t off = (uint32_t)((wrow + aRow) * 72 + kk * 16 + aK) * 2;
            LDM4(q2h[kk], sbase + off);
            LDM4(q2l[kk], sbase + 9216 * 2 + off);
        }
        __syncthreads();
    }

    float o1[8][4], o2[8][4];
    #pragma unroll
    for (int i = 0; i < 8; ++i)
        #pragma unroll
        for (int q = 0; q < 4; ++q) { o1[i][q] = 0.f; o2[i][q] = 0.f; }
    float m10 = -INFINITY, m11 = -INFINITY, l10 = 0.f, l11 = 0.f;
    float m20 = -INFINITY, m21 = -INFINITY, l20 = 0.f, l21 = 0.f;

    int nt = (m0 >> 6) + 2;
    int row0 = m0 + wrow + (lane >> 2);
    int diagRow = m0 + wrow;

    kv_prefetch(sbase, 0, 0, pKh, pKl, ldk, pVh, pVl, ldv, tid);

    for (int ct = 0; ct < nt; ++ct) {
        uint32_t bo = (uint32_t)(ct & 1) * 18432u * 2u;
        if (ct + 1 < nt) {
            kv_prefetch(sbase, (uint32_t)((ct + 1) & 1) * 18432u * 2u, (ct + 1) << 6,
                        pKh, pKl, ldk, pVh, pVl, ldv, tid);
            asm volatile("cp.async.wait_group 1;");
        } else {
            asm volatile("cp.async.wait_group 0;");
        }
        __syncthreads();
        int c0 = ct << 6;
        attn_tile<true>(sbase, bo, q1h, q1l, o1, m10, m11, l10, l11, c0, row0, diagRow, scale, lane);
        attn_tile<true>(sbase, bo, q2h, q2l, o2, m20, m21, l20, l21, c0, row0, diagRow, scale, lane);
        __syncthreads();
    }

    float i10 = 1.f / l10, i11 = 1.f / l11, i20 = 1.f / l20, i21 = 1.f / l21;
    #pragma unroll
    for (int nf = 0; nf < 8; ++nf) {
        int col = nf * 8 + (lane & 3) * 2;
        long b0 = co + (long)row0 * ldo + col;
        long b1 = co + (long)(row0 + 8) * ldo + col;
        // O1 = cval1(acc) + this
        float v0 = o1[nf][0] * i10 + O1[b0], v1 = o1[nf][1] * i10 + O1[b0 + 1];
        float v2 = o1[nf][2] * i11 + O1[b1], v3 = o1[nf][3] * i11 + O1[b1 + 1];
        O1[b0] = v0; O1[b0 + 1] = v1; O1[b1] = v2; O1[b1 + 1] = v3;
        bf h0 = __float2bfloat16(v0), h1 = __float2bfloat16(v1);
        bf h2 = __float2bfloat16(v2), h3 = __float2bfloat16(v3);
        *reinterpret_cast<uint32_t*>(O1h + b0) = packbf(__bfloat162float(h0), __bfloat162float(h1));
        *reinterpret_cast<uint32_t*>(O1h + b1) = packbf(__bfloat162float(h2), __bfloat162float(h3));
        *reinterpret_cast<uint32_t*>(O1l + b0) = packbf(v0 - __bfloat162float(h0), v1 - __bfloat162float(h1));
        *reinterpret_cast<uint32_t*>(O1l + b1) = packbf(v2 - __bfloat162float(h2), v3 - __bfloat162float(h3));
        // O2 = sval
        float w0 = o2[nf][0] * i20, w1 = o2[nf][1] * i20;
        float w2 = o2[nf][2] * i21, w3 = o2[nf][3] * i21;
        O2[b0] = w0; O2[b0 + 1] = w1; O2[b1] = w2; O2[b1 + 1] = w3;
        bf g0 = __float2bfloat16(w0), g1 = __float2bfloat16(w1);
        bf g2 = __float2bfloat16(w2), g3 = __float2bfloat16(w3);
        *reinterpret_cast<uint32_t*>(O2h + b0) = packbf(__bfloat162float(g0), __bfloat162float(g1));
        *reinterpret_cast<uint32_t*>(O2h + b1) = packbf(__bfloat162float(g2), __bfloat162float(g3));
        *reinterpret_cast<uint32_t*>(O2l + b0) = packbf(w0 - __bfloat162float(g0), w1 - __bfloat162float(g1));
        *reinterpret_cast<uint32_t*>(O2l + b1) = packbf(w2 - __bfloat162float(g2), w3 - __bfloat162float(g3));
    }
}

// ---------- G^T = SCL^2 * (k_y^T q_y)^T per head ----------
__global__ void __launch_bounds__(256) g_k(const bf* __restrict__ qh, const bf* __restrict__ ql,
                                           bf* __restrict__ goh, bf* __restrict__ gol)
{
    int z = blockIdx.x, b = z >> 3, h = z & 7;
    long kyo = (long)b * Mv * 3 * Cv + (long)h * Dv + Cv;
    long qyo = (long)b * Mv * 3 * Cv + (long)h * Dv;
    __shared__ float sky[64][65], sqy[64][65];
    int tid = threadIdx.x;
    int d2 = tid & 63, gg = tid >> 6;
    float acc[16];
    #pragma unroll
    for (int i = 0; i < 16; ++i) acc[i] = 0.f;
    for (int m0 = 0; m0 < Mv; m0 += 64) {
        #pragma unroll
        for (int i = 0; i < 16; ++i) {
            int q = tid + i * 256;
            int mm = q >> 6, dd = q & 63;
            long ik = kyo + (long)(m0 + mm) * 3 * Cv + dd;
            long iq = qyo + (long)(m0 + mm) * 3 * Cv + dd;
            sky[mm][dd] = __bfloat162float(qh[ik]) + __bfloat162float(ql[ik]);
            sqy[mm][dd] = __bfloat162float(qh[iq]) + __bfloat162float(ql[iq]);
        }
        __syncthreads();
        for (int mm = 0; mm < 64; ++mm) {
            float qv = sqy[mm][d2];
            #pragma unroll
            for (int i = 0; i < 16; ++i)
                acc[i] += sky[mm][gg * 16 + i] * qv;
        }
        __syncthreads();
    }
    long base = (long)z * 4096 + (long)d2 * 64 + gg * 16;
    #pragma unroll
    for (int i = 0; i < 16; ++i) {
        float v = acc[i] * (SCL * SCL);
        bf hh = __float2bfloat16(v);
        goh[base + i] = hh;
        gol[base + i] = __float2bfloat16(v - __bfloat162float(hh));
    }
}

// ---------- small utility kernels ----------
__global__ void split_k(const float* __restrict__ in, bf* __restrict__ oh, bf* __restrict__ ol, long n) {
    long i = (long)blockIdx.x * 256 + threadIdx.x;
    if (i < n) {
        float v = in[i]; bf h = __float2bfloat16(v);
        oh[i] = h; ol[i] = __float2bfloat16(v - __bfloat162float(h));
    }
}
__global__ void splitT_k(const float* __restrict__ in, bf* __restrict__ oh, bf* __restrict__ ol, int Kd, int Nd) {
    long i = (long)blockIdx.x * 256 + threadIdx.x;
    if (i < (long)Kd * Nd) {
        int n = (int)(i / Kd), k = (int)(i % Kd);
        float v = in[(long)k * Nd + n]; bf h = __float2bfloat16(v);
        oh[i] = h; ol[i] = __float2bfloat16(v - __bfloat162float(h));
    }
}
__global__ void gate_k(const float* __restrict__ t1, const float* __restrict__ t2,
                       const float* __restrict__ bgs, const float* __restrict__ bgc,
                       const float* __restrict__ cv, const float* __restrict__ sv,
                       bf* __restrict__ oh, bf* __restrict__ ol, long n) {
    long i = (long)blockIdx.x * 256 + threadIdx.x;
    if (i < n) {
        int c = (int)(i & (Cv - 1));
        float g1 = 1.f / (1.f + __expf(-(t1[i] + bgs[c])));
        float g2 = 1.f / (1.f + __expf(-(t2[i] + bgc[c])));
        float v = g1 * cv[i] + g2 * sv[i];
        bf h = __float2bfloat16(v);
        oh[i] = h; ol[i] = __float2bfloat16(v - __bfloat162float(h));
    }
}

// ------------------------------------------------------------------------------
extern "C" void kernel_launch(void* const* d_in, const int* in_sizes, int n_in,
                              void* d_out, int out_size)
{
    const float* x      = (const float*)d_in[0];
    const float* y      = (const float*)d_in[1];
    const float* Wqkv_x = (const float*)d_in[3];
    const float* bqkv_x = (const float*)d_in[4];
    const float* Wqkv_y = (const float*)d_in[5];
    const float* bqkv_y = (const float*)d_in[6];
    const float* Wgs    = (const float*)d_in[7];
    const float* bgs    = (const float*)d_in[8];
    const float* Wgc    = (const float*)d_in[9];
    const float* bgc    = (const float*)d_in[10];
    const float* Wp     = (const float*)d_in[11];
    const float* bp     = (const float*)d_in[12];
    float* out = (float*)d_out;

    bf *gh, *gl; float* gf;
    cudaGetSymbolAddress((void**)&gh, g_h);
    cudaGetSymbolAddress((void**)&gl, g_l);
    cudaGetSymbolAddress((void**)&gf, g_f);

    const int FASM = 2 * 18432 * 2;   // 73728 B dynamic smem
    cudaFuncSetAttribute((const void*)fa_k,  cudaFuncAttributeMaxDynamicSharedMemorySize, FASM);
    cudaFuncSetAttribute((const void*)fa2_k, cudaFuncAttributeMaxDynamicSharedMemorySize, FASM);

    dim3 blk(256);
    long nTC = (long)BBv * Tv * Cv;

    // input / weight splits
    split_k<<<(unsigned)((nTC + 255) / 256), blk>>>(x, gh + oXB, gl + oXB, nTC);
    split_k<<<(unsigned)((BBv*Mv*Cv + 255) / 256), blk>>>(y, gh + oYB, gl + oYB, (long)BBv*Mv*Cv);
    splitT_k<<<(unsigned)((Cv*3*Cv + 255) / 256), blk>>>(Wqkv_x, gh + oWQX, gl + oWQX, Cv, 3*Cv);
    splitT_k<<<(unsigned)((Cv*3*Cv + 255) / 256), blk>>>(Wqkv_y, gh + oWQY, gl + oWQY, Cv, 3*Cv);
    splitT_k<<<(unsigned)((Cv*Cv + 255) / 256), blk>>>(Wgs, gh + oWGS, gl + oWGS, Cv, Cv);
    splitT_k<<<(unsigned)((Cv*Cv + 255) / 256), blk>>>(Wgc, gh + oWGC, gl + oWGC, Cv, Cv);
    splitT_k<<<(unsigned)((Cv*Cv + 255) / 256), blk>>>(Wp,  gh + oWP,  gl + oWP,  Cv, Cv);

    // qkv projections
    hg<128,false,true,true><<<dim3(12,32,1), blk>>>(
        gh+oXB, gl+oXB, Cv, 0,0, gh+oWQX, gl+oWQX, Cv, 0,0,
        nullptr, gh+oQKVX, gl+oQKVX, 3*Cv, 0,0, bqkv_x, Cv, 1, 1.0f);
    hg<128,false,true,true><<<dim3(12,8,1), blk>>>(
        gh+oYB, gl+oYB, Cv, 0,0, gh+oWQY, gl+oWQY, Cv, 0,0,
        nullptr, gh+oQKVY, gl+oQKVY, 3*Cv, 0,0, bqkv_y, Cv, 1, 1.0f);

    // G^T then qxG
    g_k<<<BHv, blk>>>(gh+oQKVY, gl+oQKVY, gh+oGT, gl+oGT);
    hg<64,false,true,false><<<dim3(1,16,16), blk>>>(
        gh+oQKVX, gl+oQKVX, 3*Cv, (long)Tv*3*Cv, (long)Dv,
        gh+oGT, gl+oGT, 64, (long)Hv*Dv*Dv, (long)Dv*Dv,
        nullptr, gh+oQXG, gl+oQXG, Dv, (long)Hv*Tv*Dv, (long)Tv*Dv, nullptr, Dv, Hv, 1.0f);

    // cval1 = softmax(q_x k_y^T) v_y  (fused, non-causal; V direct from qkv_y)
    fa_k<<<dim3(16,16), blk, FASM>>>(
        gh+oQKVX, gl+oQKVX, 3*Cv, (long)Tv*3*Cv, (long)Dv,
        gh+oQKVY+Cv, gl+oQKVY+Cv, 3*Cv, (long)Mv*3*Cv, (long)Dv,
        gh+oQKVY+2*Cv, gl+oQKVY+2*Cv, 3*Cv, (long)Mv*3*Cv, (long)Dv,
        Mv, gf+fC1, Cv, (long)Tv*Cv, (long)Dv, SCL);

    // dual-Q causal: cval = cval1 + softmax(qxG k_x^T) v_x ; sval = softmax(q_x k_x^T) v_x
    fa2_k<<<dim3(16,16), blk, FASM>>>(
        gh+oQXG, gl+oQXG, Dv, (long)Hv*Tv*Dv, (long)Tv*Dv,
        gh+oQKVX, gl+oQKVX, 3*Cv, (long)Tv*3*Cv, (long)Dv,
        gh+oQKVX+Cv, gl+oQKVX+Cv, 3*Cv, (long)Tv*3*Cv, (long)Dv,
        gh+oQKVX+2*Cv, gl+oQKVX+2*Cv, 3*Cv, (long)Tv*3*Cv, (long)Dv,
        gf+fC1, gh+oCV, gl+oCV,
        gf+fSV, gh+oSV, gl+oSV,
        Cv, (long)Tv*Cv, (long)Dv, SCL);

    // gates: batched z=2 (t1 = sval@Wgs, t2 = cval@Wgc), biases folded into gate_k
    hg<128,true,false,false><<<dim3(4,32,2), blk>>>(
        gh+oSV, gl+oSV, Cv, 0, nTC,
        gh+oWGS, gl+oWGS, Cv, 0, (long)Cv*Cv,
        gf+fT1, nullptr, nullptr, Cv, 0, nTC, nullptr, Cv, 2, 1.0f);

    gate_k<<<(unsigned)((nTC + 255) / 256), blk>>>(
        gf+fT1, gf+fT2, bgs, bgc, gf+fC1, gf+fSV, gh+oT3, gl+oT3, nTC);

    // out = t3 @ Wp + bp
    hg<128,true,false,true><<<dim3(4,32,1), blk>>>(
        gh+oT3, gl+oT3, Cv, 0,0, gh+oWP, gl+oWP, Cv, 0,0,
        out, nullptr, nullptr, Cv, 0,0, bp, Cv, 1, 1.0f);
}